// round 5
// baseline (speedup 1.0000x reference)
#include <cuda_runtime.h>
#include <cuda_bf16.h>
#include <math.h>
#include <stdint.h>

#define D_MODEL   4096
#define NE        64
#define NTOK_MAX  32768
#define NCAND     8

// ---------------- scratch (__device__ globals: allocation-free) ----------------
__device__ __align__(16) __nv_bfloat16 g_Wbf[NE * D_MODEL];          // 512 KB
__device__ __align__(16) unsigned char g_cand[NTOK_MAX * NCAND];     // 256 KB

// ---------------- helpers ----------------
__device__ __forceinline__ unsigned s2u(const void* p) {
    return (unsigned)__cvta_generic_to_shared(p);
}
__device__ __forceinline__ void cp16(unsigned sdst, const void* g) {
    asm volatile("cp.async.cg.shared.global [%0], [%1], 16;\n" :: "r"(sdst), "l"(g));
}
__device__ __forceinline__ void cp_commit() { asm volatile("cp.async.commit_group;\n"); }
__device__ __forceinline__ void cp_wait(int n) {
    if (n == 0) asm volatile("cp.async.wait_group 0;\n");
    else        asm volatile("cp.async.wait_group 1;\n");
}
__device__ __forceinline__ unsigned f2bf2(float2 v) {
    __nv_bfloat162 p = __float22bfloat162_rn(v);
    return *(unsigned*)&p;
}
// mma.sync m16n8k16 row.col f32 += bf16*bf16
__device__ __forceinline__ void mma16816(float c[4], unsigned a0, unsigned a1,
                                         unsigned a2, unsigned a3,
                                         unsigned b0, unsigned b1) {
    asm volatile(
        "mma.sync.aligned.m16n8k16.row.col.f32.bf16.bf16.f32 "
        "{%0,%1,%2,%3}, {%4,%5,%6,%7}, {%8,%9}, {%0,%1,%2,%3};"
        : "+f"(c[0]), "+f"(c[1]), "+f"(c[2]), "+f"(c[3])
        : "r"(a0), "r"(a1), "r"(a2), "r"(a3), "r"(b0), "r"(b1));
}

// ================= K0: W fp32 -> bf16 =================
__global__ void k0_convert_w(const float* __restrict__ W) {
    int g = blockIdx.x * blockDim.x + threadIdx.x;     // float4 index, 65536 total
    float4 v = *(const float4*)(W + (size_t)g * 4);
    unsigned p0 = f2bf2(make_float2(v.x, v.y));
    unsigned p1 = f2bf2(make_float2(v.z, v.w));
    *(uint2*)&g_Wbf[(size_t)g * 4] = make_uint2(p0, p1);
}

// ================= K1: bf16 HMMA screen -> top-8 candidates =================
// CTA: 128 tokens x 64 experts. warp w -> tokens 16w..16w+15, all 64 experts.
#define K1_KB     256                       // K slice of W staged in smem
#define K1_STAGES (D_MODEL / K1_KB)         // 16
#define WROW_BF   264                       // 256 bf16 + 8 pad  (528 B row)
#define WROW_B    (WROW_BF * 2)
#define WBUF_B    (NE * WROW_B)             // 33792
#define K1_SMEM   (2 * WBUF_B)              // 67584 (scores [128][68] alias: 34816)

__global__ __launch_bounds__(256, 2)
void k1_approx(const float* __restrict__ X, const float* __restrict__ b, int n_tokens)
{
    extern __shared__ __align__(16) char dsm[];
    __shared__ float s_bias[NE];

    const int tid  = threadIdx.x;
    const int wid  = tid >> 5;
    const int lane = tid & 31;
    const int row0 = blockIdx.x * 128;

    if (tid < NE) s_bias[tid] = b[tid];

    // prefetch W stage into buf: 64 rows x 32 granules(16B) = 2048, 8/thread
    auto prefetch = [&](int t, int buf) {
        const int kb = t * K1_KB;
        unsigned base = s2u(dsm) + buf * WBUF_B;
        #pragma unroll
        for (int j = 0; j < 8; j++) {
            int idx = tid + j * 256;          // 0..2047
            int e = idx >> 5;                 // expert 0..63
            int q = idx & 31;                 // 16B granule
            cp16(base + (unsigned)e * WROW_B + (unsigned)q * 16,
                 g_Wbf + (size_t)e * D_MODEL + kb + q * 8);
        }
        cp_commit();
    };

    // A-fragment global base: row = row0 + 16*wid + (lane>>2), col pair 2*(lane&3)
    const float* xr0 = X + (size_t)(row0 + 16 * wid + (lane >> 2)) * D_MODEL
                         + 2 * (lane & 3);
    const float* xr8 = xr0 + (size_t)8 * D_MODEL;

    float acc[8][4];
    #pragma unroll
    for (int nt = 0; nt < 8; nt++)
        #pragma unroll
        for (int j = 0; j < 4; j++) acc[nt][j] = 0.0f;

    prefetch(0, 0);
    int buf = 0;

    for (int t = 0; t < K1_STAGES; t++) {
        const bool has_next = (t + 1 < K1_STAGES);
        if (has_next) prefetch(t + 1, buf ^ 1);
        cp_wait(has_next ? 1 : 0);
        __syncthreads();

        const char* wB = dsm + buf * WBUF_B;

        #pragma unroll 4
        for (int ks = 0; ks < K1_KB / 16; ks++) {
            const int k = t * K1_KB + ks * 16;
            // A fragment: (0,0) (8,0) (0,8) (8,8) blocks
            unsigned a0 = f2bf2(*(const float2*)(xr0 + k));
            unsigned a1 = f2bf2(*(const float2*)(xr8 + k));
            unsigned a2 = f2bf2(*(const float2*)(xr0 + k + 8));
            unsigned a3 = f2bf2(*(const float2*)(xr8 + k + 8));
            #pragma unroll
            for (int nt = 0; nt < 8; nt++) {
                const char* wrow = wB + (nt * 8 + (lane >> 2)) * WROW_B
                                      + ks * 32 + 4 * (lane & 3);
                unsigned b0 = *(const unsigned*)(wrow);        // k pair
                unsigned b1 = *(const unsigned*)(wrow + 16);   // k+8 pair
                mma16816(acc[nt], a0, a1, a2, a3, b0, b1);
            }
        }
        __syncthreads();
        buf ^= 1;
    }

    // ---- scores to smem (alias W buffers) ----
    float* sc = (float*)dsm;                  // [128][68]
    {
        int r = 16 * wid + (lane >> 2);
        int cb = 2 * (lane & 3);
        #pragma unroll
        for (int nt = 0; nt < 8; nt++) {
            int c = 8 * nt + cb;
            sc[r * 68 + c]           = acc[nt][0];
            sc[r * 68 + c + 1]       = acc[nt][1];
            sc[(r + 8) * 68 + c]     = acc[nt][2];
            sc[(r + 8) * 68 + c + 1] = acc[nt][3];
        }
    }
    __syncthreads();

    // ---- per-token top-8 (strict '>' keeps lowest index on ties, like lax.top_k) ----
    if (tid < 128) {
        float sv[NCAND];
        int   si[NCAND];
        #pragma unroll
        for (int j = 0; j < NCAND; j++) { sv[j] = -INFINITY; si[j] = 0; }
        #pragma unroll
        for (int e = 0; e < NE; e++) {
            float cs = sc[tid * 68 + e] + s_bias[e];
            int ci = e;
            #pragma unroll
            for (int j = 0; j < NCAND; j++) {
                if (cs > sv[j]) {
                    float tf = sv[j]; int ti = si[j];
                    sv[j] = cs; si[j] = ci; cs = tf; ci = ti;
                }
            }
        }
        int token = row0 + tid;
        unsigned lo = (unsigned)si[0] | ((unsigned)si[1] << 8) |
                      ((unsigned)si[2] << 16) | ((unsigned)si[3] << 24);
        unsigned hi = (unsigned)si[4] | ((unsigned)si[5] << 8) |
                      ((unsigned)si[6] << 16) | ((unsigned)si[7] << 24);
        *(uint2*)&g_cand[(size_t)token * NCAND] = make_uint2(lo, hi);
    }
}

// ================= K2: exact fp32 rescore of top-8 (R2-proven numerics) =================
#define K2_BK 32
__global__ __launch_bounds__(128, 4)
void k2_exact(const float* __restrict__ X, const float* __restrict__ W,
              const float* __restrict__ b, float* __restrict__ out, int n_tokens)
{
    __shared__ float Xs[128][36];
    __shared__ float Ws[64][36];
    __shared__ float bs[NE];

    const int tid  = threadIdx.x;
    const int tok0 = blockIdx.x * 128;
    const int tok  = tok0 + tid;

    if (tid < NE) bs[tid] = b[tid];

    uint2 cd = *(const uint2*)&g_cand[(size_t)tok * NCAND];
    int e[NCAND];
    #pragma unroll
    for (int j = 0; j < 4; j++) e[j]     = (cd.x >> (8 * j)) & 63;
    #pragma unroll
    for (int j = 0; j < 4; j++) e[4 + j] = (cd.y >> (8 * j)) & 63;

    float sum[NCAND], cmp[NCAND];
    #pragma unroll
    for (int j = 0; j < NCAND; j++) { sum[j] = 0.0f; cmp[j] = 0.0f; }

    for (int kb = 0; kb < D_MODEL; kb += K2_BK) {
        __syncthreads();   // prior tile fully consumed
        #pragma unroll
        for (int i = 0; i < 8; i++) {
            int idx = tid + i * 128;                     // 0..1023 float4
            int r = idx >> 3, c4 = idx & 7;
            *(float4*)&Xs[r][c4 * 4] =
                *(const float4*)(X + (size_t)(tok0 + r) * D_MODEL + kb + c4 * 4);
        }
        #pragma unroll
        for (int i = 0; i < 4; i++) {
            int idx = tid + i * 128;                     // 0..511 float4
            int r = idx >> 3, c4 = idx & 7;
            *(float4*)&Ws[r][c4 * 4] =
                *(const float4*)(W + (size_t)r * D_MODEL + kb + c4 * 4);
        }
        __syncthreads();

        float c8[NCAND];
        #pragma unroll
        for (int j = 0; j < NCAND; j++) c8[j] = 0.0f;

        #pragma unroll
        for (int k4 = 0; k4 < K2_BK / 4; k4++) {
            float4 xq = *(const float4*)&Xs[tid][k4 * 4];
            #pragma unroll
            for (int j = 0; j < NCAND; j++) {
                float4 wq = *(const float4*)&Ws[e[j]][k4 * 4];
                c8[j] = fmaf(xq.x, wq.x, c8[j]);
                c8[j] = fmaf(xq.y, wq.y, c8[j]);
                c8[j] = fmaf(xq.z, wq.z, c8[j]);
                c8[j] = fmaf(xq.w, wq.w, c8[j]);
            }
        }
        // Kahan merge (rn intrinsics: no contraction/reassociation)
        #pragma unroll
        for (int j = 0; j < NCAND; j++) {
            float y = __fsub_rn(c8[j], cmp[j]);
            float s = __fadd_rn(sum[j], y);
            cmp[j] = __fsub_rn(__fsub_rn(s, sum[j]), y);
            sum[j] = s;
        }
    }

    // ---- exact top-2 among candidates (tie-break: lower expert index) ----
    float m1 = -INFINITY, m2 = -INFINITY;
    int   i1 = 0,         i2 = 0;
    #pragma unroll
    for (int j = 0; j < NCAND; j++) {
        float s = __fadd_rn(__fsub_rn(sum[j], cmp[j]), bs[e[j]]);
        if (s > m1 || (s == m1 && e[j] < i1)) {
            m2 = m1; i2 = i1; m1 = s; i1 = e[j];
        } else if (s > m2 || (s == m2 && e[j] < i2)) {
            m2 = s; i2 = e[j];
        }
    }
    float e2v = expf(m2 - m1);
    float inv = 1.0f / (1.0f + e2v);

    out[(size_t)tok * 2 + 0] = inv;
    out[(size_t)tok * 2 + 1] = e2v * inv;
    size_t idx_base = (size_t)n_tokens * 2;
    out[idx_base + (size_t)tok * 2 + 0] = (float)i1;
    out[idx_base + (size_t)tok * 2 + 1] = (float)i2;
}

// ================= launch =================
extern "C" void kernel_launch(void* const* d_in, const int* in_sizes, int n_in,
                              void* d_out, int out_size)
{
    const float* X = (const float*)d_in[0];   // [N, 4096]
    const float* W = (const float*)d_in[1];   // [64, 4096]
    const float* b = (const float*)d_in[2];   // [64]
    float* out = (float*)d_out;

    int n_tokens = in_sizes[0] / D_MODEL;     // 32768

    cudaFuncSetAttribute(k1_approx,
                         cudaFuncAttributeMaxDynamicSharedMemorySize, K1_SMEM);

    k0_convert_w<<<256, 256>>>(W);
    k1_approx<<<n_tokens / 128, 256, K1_SMEM>>>(X, b, n_tokens);
    k2_exact<<<n_tokens / 128, 128>>>(X, W, b, out, n_tokens);
}

// round 6
// speedup vs baseline: 1.8023x; 1.8023x over previous
#include <cuda_runtime.h>
#include <cuda_bf16.h>
#include <math.h>
#include <stdint.h>

#define D_MODEL   4096
#define NE        64
#define NTOK_MAX  32768
#define NCAND     8     // stored by screen (sorted desc)
#define NC2       6     // rescored exactly

// ---------------- scratch (__device__ globals: allocation-free) ----------------
__device__ __align__(16) __nv_bfloat16 g_Wbf[NE * D_MODEL];          // 512 KB
__device__ __align__(16) unsigned char g_cand[NTOK_MAX * NCAND];     // 256 KB

// ---------------- helpers ----------------
__device__ __forceinline__ unsigned s2u(const void* p) {
    return (unsigned)__cvta_generic_to_shared(p);
}
__device__ __forceinline__ void cp16(unsigned sdst, const void* g) {
    asm volatile("cp.async.cg.shared.global [%0], [%1], 16;\n" :: "r"(sdst), "l"(g));
}
__device__ __forceinline__ void cp_commit() { asm volatile("cp.async.commit_group;\n"); }
__device__ __forceinline__ void cp_wait(int n) {
    if (n == 0) asm volatile("cp.async.wait_group 0;\n");
    else        asm volatile("cp.async.wait_group 1;\n");
}
__device__ __forceinline__ unsigned f2bf2(float2 v) {
    __nv_bfloat162 p = __float22bfloat162_rn(v);
    return *(unsigned*)&p;
}
__device__ __forceinline__ void mma16816(float c[4], unsigned a0, unsigned a1,
                                         unsigned a2, unsigned a3,
                                         unsigned b0, unsigned b1) {
    asm volatile(
        "mma.sync.aligned.m16n8k16.row.col.f32.bf16.bf16.f32 "
        "{%0,%1,%2,%3}, {%4,%5,%6,%7}, {%8,%9}, {%0,%1,%2,%3};"
        : "+f"(c[0]), "+f"(c[1]), "+f"(c[2]), "+f"(c[3])
        : "r"(a0), "r"(a1), "r"(a2), "r"(a3), "r"(b0), "r"(b1));
}

// ================= K0: W fp32 -> bf16 =================
__global__ void k0_convert_w(const float* __restrict__ W) {
    int g = blockIdx.x * blockDim.x + threadIdx.x;     // float4 index, 65536 total
    float4 v = *(const float4*)(W + (size_t)g * 4);
    unsigned p0 = f2bf2(make_float2(v.x, v.y));
    unsigned p1 = f2bf2(make_float2(v.z, v.w));
    *(uint2*)&g_Wbf[(size_t)g * 4] = make_uint2(p0, p1);
}

// ================= K1: bf16 HMMA screen -> top-8 candidates (proven in R5) =================
#define K1_KB     256
#define K1_STAGES (D_MODEL / K1_KB)         // 16
#define WROW_BF   264                       // 256 bf16 + 8 pad
#define WROW_B    (WROW_BF * 2)
#define WBUF_B    (NE * WROW_B)             // 33792
#define K1_SMEM   (2 * WBUF_B)              // 67584

__global__ __launch_bounds__(256, 2)
void k1_approx(const float* __restrict__ X, const float* __restrict__ b, int n_tokens)
{
    extern __shared__ __align__(16) char dsm[];
    __shared__ float s_bias[NE];

    const int tid  = threadIdx.x;
    const int wid  = tid >> 5;
    const int lane = tid & 31;
    const int row0 = blockIdx.x * 128;

    if (tid < NE) s_bias[tid] = b[tid];

    auto prefetch = [&](int t, int buf) {
        const int kb = t * K1_KB;
        unsigned base = s2u(dsm) + buf * WBUF_B;
        #pragma unroll
        for (int j = 0; j < 8; j++) {
            int idx = tid + j * 256;
            int e = idx >> 5;
            int q = idx & 31;
            cp16(base + (unsigned)e * WROW_B + (unsigned)q * 16,
                 g_Wbf + (size_t)e * D_MODEL + kb + q * 8);
        }
        cp_commit();
    };

    const float* xr0 = X + (size_t)(row0 + 16 * wid + (lane >> 2)) * D_MODEL
                         + 2 * (lane & 3);
    const float* xr8 = xr0 + (size_t)8 * D_MODEL;

    float acc[8][4];
    #pragma unroll
    for (int nt = 0; nt < 8; nt++)
        #pragma unroll
        for (int j = 0; j < 4; j++) acc[nt][j] = 0.0f;

    prefetch(0, 0);
    int buf = 0;

    for (int t = 0; t < K1_STAGES; t++) {
        const bool has_next = (t + 1 < K1_STAGES);
        if (has_next) prefetch(t + 1, buf ^ 1);
        cp_wait(has_next ? 1 : 0);
        __syncthreads();

        const char* wB = dsm + buf * WBUF_B;

        #pragma unroll 4
        for (int ks = 0; ks < K1_KB / 16; ks++) {
            const int k = t * K1_KB + ks * 16;
            unsigned a0 = f2bf2(*(const float2*)(xr0 + k));
            unsigned a1 = f2bf2(*(const float2*)(xr8 + k));
            unsigned a2 = f2bf2(*(const float2*)(xr0 + k + 8));
            unsigned a3 = f2bf2(*(const float2*)(xr8 + k + 8));
            #pragma unroll
            for (int nt = 0; nt < 8; nt++) {
                const char* wrow = wB + (nt * 8 + (lane >> 2)) * WROW_B
                                      + ks * 32 + 4 * (lane & 3);
                unsigned b0 = *(const unsigned*)(wrow);
                unsigned b1 = *(const unsigned*)(wrow + 16);
                mma16816(acc[nt], a0, a1, a2, a3, b0, b1);
            }
        }
        __syncthreads();
        buf ^= 1;
    }

    float* sc = (float*)dsm;                  // [128][68]
    {
        int r = 16 * wid + (lane >> 2);
        int cb = 2 * (lane & 3);
        #pragma unroll
        for (int nt = 0; nt < 8; nt++) {
            int c = 8 * nt + cb;
            sc[r * 68 + c]           = acc[nt][0];
            sc[r * 68 + c + 1]       = acc[nt][1];
            sc[(r + 8) * 68 + c]     = acc[nt][2];
            sc[(r + 8) * 68 + c + 1] = acc[nt][3];
        }
    }
    __syncthreads();

    if (tid < 128) {
        float sv[NCAND];
        int   si[NCAND];
        #pragma unroll
        for (int j = 0; j < NCAND; j++) { sv[j] = -INFINITY; si[j] = 0; }
        #pragma unroll
        for (int e = 0; e < NE; e++) {
            float cs = sc[tid * 68 + e] + s_bias[e];
            int ci = e;
            #pragma unroll
            for (int j = 0; j < NCAND; j++) {
                if (cs > sv[j]) {
                    float tf = sv[j]; int ti = si[j];
                    sv[j] = cs; si[j] = ci; cs = tf; ci = ti;
                }
            }
        }
        int token = row0 + tid;
        unsigned lo = (unsigned)si[0] | ((unsigned)si[1] << 8) |
                      ((unsigned)si[2] << 16) | ((unsigned)si[3] << 24);
        unsigned hi = (unsigned)si[4] | ((unsigned)si[5] << 8) |
                      ((unsigned)si[6] << 16) | ((unsigned)si[7] << 24);
        *(uint2*)&g_cand[(size_t)token * NCAND] = make_uint2(lo, hi);
    }
}

// ================= K2 v2: conflict-free exact rescore of top-6 =================
// CTA: 512 threads, 64 tokens. Warp = 4 tokens (tt=lane>>3) x 8 K-sublanes (kk=lane&7).
// W staged fully (64 experts) per 64-wide K tile, fp32, double-buffered.
// LDS phases are row-constant -> zero bank conflicts.
#define K2_KB     64
#define K2_TILES  (D_MODEL / K2_KB)      // 64
#define K2_WROW   68                     // 64 + 4 pad floats

__global__ __launch_bounds__(512, 2)
void k2_exact(const float* __restrict__ X, const float* __restrict__ W,
              const float* __restrict__ b, float* __restrict__ out, int n_tokens)
{
    __shared__ float Ws[2][NE][K2_WROW];
    __shared__ float bs[NE];

    const int tid  = threadIdx.x;
    const int wid  = tid >> 5;          // 0..15
    const int lane = tid & 31;
    const int tt   = lane >> 3;         // 0..3  token-in-warp
    const int kk   = lane & 7;          // 0..7  K sublane
    const int tok0 = blockIdx.x * 64;
    const int token = tok0 + 4 * wid + tt;

    if (tid < NE) bs[tid] = b[tid];

    // prefetch full W K-slice: 64 rows x 16 granules(16B) = 1024, 2 per thread
    auto prefetch = [&](int t, int buf) {
        const int kb = t * K2_KB;
        unsigned base = s2u(&Ws[buf][0][0]);
        #pragma unroll
        for (int j = 0; j < 2; j++) {
            int idx = tid + j * 512;            // 0..1023
            int e = idx >> 4;                   // 0..63
            int q = idx & 15;                   // 16B granule
            cp16(base + ((unsigned)e * K2_WROW + (unsigned)q * 4) * 4,
                 W + (size_t)e * D_MODEL + kb + q * 4);
        }
        cp_commit();
    };

    // candidates (first 6 of the stored, sorted-desc 8)
    uint2 cd = *(const uint2*)&g_cand[(size_t)token * NCAND];
    int e[NC2];
    #pragma unroll
    for (int j = 0; j < 4; j++) e[j] = (cd.x >> (8 * j)) & 63;
    e[4] = cd.y & 63;
    e[5] = (cd.y >> 8) & 63;

    float sum[NC2], cmp[NC2];
    #pragma unroll
    for (int j = 0; j < NC2; j++) { sum[j] = 0.0f; cmp[j] = 0.0f; }

    const float* xrow = X + (size_t)token * D_MODEL;

    prefetch(0, 0);
    int buf = 0;

    for (int t = 0; t < K2_TILES; t++) {
        const bool has_next = (t + 1 < K2_TILES);
        if (has_next) prefetch(t + 1, buf ^ 1);
        cp_wait(has_next ? 1 : 0);
        __syncthreads();

        const int kb = t * K2_KB;
        // X: lane kk covers k = kb + 4kk + {0..3} and kb + 32 + 4kk + {0..3}
        float4 xa = *(const float4*)(xrow + kb + 4 * kk);
        float4 xb = *(const float4*)(xrow + kb + 32 + 4 * kk);

        float c6[NC2];
        #pragma unroll
        for (int j = 0; j < NC2; j++) {
            const float* wr = &Ws[buf][e[j]][0];
            float4 wa = *(const float4*)(wr + 4 * kk);        // conflict-free
            float4 wb = *(const float4*)(wr + 32 + 4 * kk);
            float s = xa.x * wa.x;
            s = fmaf(xa.y, wa.y, s);
            s = fmaf(xa.z, wa.z, s);
            s = fmaf(xa.w, wa.w, s);
            s = fmaf(xb.x, wb.x, s);
            s = fmaf(xb.y, wb.y, s);
            s = fmaf(xb.z, wb.z, s);
            s = fmaf(xb.w, wb.w, s);
            c6[j] = s;
        }
        // Kahan merge (rn intrinsics: no contraction/reassociation)
        #pragma unroll
        for (int j = 0; j < NC2; j++) {
            float y = __fsub_rn(c6[j], cmp[j]);
            float s = __fadd_rn(sum[j], y);
            cmp[j] = __fsub_rn(__fsub_rn(s, sum[j]), y);
            sum[j] = s;
        }

        __syncthreads();
        buf ^= 1;
    }

    // compensated per-lane partials, then reduce across the 8 kk-lanes
    float s6[NC2];
    #pragma unroll
    for (int j = 0; j < NC2; j++) {
        s6[j] = __fadd_rn(sum[j], __fsub_rn(0.0f, cmp[j]));
        s6[j] = __fadd_rn(s6[j], __shfl_xor_sync(0xFFFFFFFFu, s6[j], 1));
        s6[j] = __fadd_rn(s6[j], __shfl_xor_sync(0xFFFFFFFFu, s6[j], 2));
        s6[j] = __fadd_rn(s6[j], __shfl_xor_sync(0xFFFFFFFFu, s6[j], 4));
    }

    if (kk == 0) {
        float m1 = -INFINITY, m2 = -INFINITY;
        int   i1 = 0,         i2 = 0;
        #pragma unroll
        for (int j = 0; j < NC2; j++) {
            float s = __fadd_rn(s6[j], bs[e[j]]);
            if (s > m1 || (s == m1 && e[j] < i1)) {
                m2 = m1; i2 = i1; m1 = s; i1 = e[j];
            } else if (s > m2 || (s == m2 && e[j] < i2)) {
                m2 = s; i2 = e[j];
            }
        }
        float e2v = expf(m2 - m1);
        float inv = 1.0f / (1.0f + e2v);

        out[(size_t)token * 2 + 0] = inv;
        out[(size_t)token * 2 + 1] = e2v * inv;
        size_t idx_base = (size_t)n_tokens * 2;
        out[idx_base + (size_t)token * 2 + 0] = (float)i1;
        out[idx_base + (size_t)token * 2 + 1] = (float)i2;
    }
}

// ================= launch =================
extern "C" void kernel_launch(void* const* d_in, const int* in_sizes, int n_in,
                              void* d_out, int out_size)
{
    const float* X = (const float*)d_in[0];   // [N, 4096]
    const float* W = (const float*)d_in[1];   // [64, 4096]
    const float* b = (const float*)d_in[2];   // [64]
    float* out = (float*)d_out;

    int n_tokens = in_sizes[0] / D_MODEL;     // 32768

    cudaFuncSetAttribute(k1_approx,
                         cudaFuncAttributeMaxDynamicSharedMemorySize, K1_SMEM);

    k0_convert_w<<<256, 256>>>(W);
    k1_approx<<<n_tokens / 128, 256, K1_SMEM>>>(X, b, n_tokens);
    k2_exact<<<n_tokens / 64, 512>>>(X, W, b, out, n_tokens);
}

// round 7
// speedup vs baseline: 1.8940x; 1.0509x over previous
#include <cuda_runtime.h>
#include <cuda_bf16.h>
#include <math.h>
#include <stdint.h>

#define D_MODEL   4096
#define NE        64
#define NTOK_MAX  32768
#define NCAND     8     // stored by screen (sorted desc)
#define NC_WIN    0.05f // screen-score window for adaptive rescore width

// ---------------- scratch (__device__ globals: allocation-free) ----------------
__device__ __align__(16) __nv_bfloat16 g_Wbf[NE * D_MODEL];          // 512 KB
__device__ __align__(16) unsigned char g_cand[NTOK_MAX * NCAND];     // 256 KB
__device__ unsigned char g_ncand[NTOK_MAX];                          // 32 KB

// ---------------- helpers ----------------
__device__ __forceinline__ unsigned s2u(const void* p) {
    return (unsigned)__cvta_generic_to_shared(p);
}
__device__ __forceinline__ void cp16(unsigned sdst, const void* g) {
    asm volatile("cp.async.cg.shared.global [%0], [%1], 16;\n" :: "r"(sdst), "l"(g));
}
__device__ __forceinline__ void cp_commit() { asm volatile("cp.async.commit_group;\n"); }
__device__ __forceinline__ void cp_wait(int n) {
    if (n == 0) asm volatile("cp.async.wait_group 0;\n");
    else        asm volatile("cp.async.wait_group 1;\n");
}
__device__ __forceinline__ unsigned f2bf2(float2 v) {
    __nv_bfloat162 p = __float22bfloat162_rn(v);
    return *(unsigned*)&p;
}
__device__ __forceinline__ void mma16816(float c[4], unsigned a0, unsigned a1,
                                         unsigned a2, unsigned a3,
                                         unsigned b0, unsigned b1) {
    asm volatile(
        "mma.sync.aligned.m16n8k16.row.col.f32.bf16.bf16.f32 "
        "{%0,%1,%2,%3}, {%4,%5,%6,%7}, {%8,%9}, {%0,%1,%2,%3};"
        : "+f"(c[0]), "+f"(c[1]), "+f"(c[2]), "+f"(c[3])
        : "r"(a0), "r"(a1), "r"(a2), "r"(a3), "r"(b0), "r"(b1));
}

// ================= K0: W fp32 -> bf16 =================
__global__ void k0_convert_w(const float* __restrict__ W) {
    int g = blockIdx.x * blockDim.x + threadIdx.x;
    float4 v = *(const float4*)(W + (size_t)g * 4);
    unsigned p0 = f2bf2(make_float2(v.x, v.y));
    unsigned p1 = f2bf2(make_float2(v.z, v.w));
    *(uint2*)&g_Wbf[(size_t)g * 4] = make_uint2(p0, p1);
}

// ================= K1: bf16 HMMA screen -> top-8 candidates + nc =================
#define K1_KB     256
#define K1_STAGES (D_MODEL / K1_KB)
#define WROW_BF   264
#define WROW_B    (WROW_BF * 2)
#define WBUF_B    (NE * WROW_B)             // 33792
#define K1_SMEM   (2 * WBUF_B)              // 67584

__global__ __launch_bounds__(256, 2)
void k1_approx(const float* __restrict__ X, const float* __restrict__ b, int n_tokens)
{
    extern __shared__ __align__(16) char dsm[];
    __shared__ float s_bias[NE];

    const int tid  = threadIdx.x;
    const int wid  = tid >> 5;
    const int lane = tid & 31;
    const int row0 = blockIdx.x * 128;

    if (tid < NE) s_bias[tid] = b[tid];

    auto prefetch = [&](int t, int buf) {
        const int kb = t * K1_KB;
        unsigned base = s2u(dsm) + buf * WBUF_B;
        #pragma unroll
        for (int j = 0; j < 8; j++) {
            int idx = tid + j * 256;
            int e = idx >> 5;
            int q = idx & 31;
            cp16(base + (unsigned)e * WROW_B + (unsigned)q * 16,
                 g_Wbf + (size_t)e * D_MODEL + kb + q * 8);
        }
        cp_commit();
    };

    const float* xr0 = X + (size_t)(row0 + 16 * wid + (lane >> 2)) * D_MODEL
                         + 2 * (lane & 3);
    const float* xr8 = xr0 + (size_t)8 * D_MODEL;

    float acc[8][4];
    #pragma unroll
    for (int nt = 0; nt < 8; nt++)
        #pragma unroll
        for (int j = 0; j < 4; j++) acc[nt][j] = 0.0f;

    prefetch(0, 0);
    int buf = 0;

    for (int t = 0; t < K1_STAGES; t++) {
        const bool has_next = (t + 1 < K1_STAGES);
        if (has_next) prefetch(t + 1, buf ^ 1);
        cp_wait(has_next ? 1 : 0);
        __syncthreads();

        const char* wB = dsm + buf * WBUF_B;

        #pragma unroll 4
        for (int ks = 0; ks < K1_KB / 16; ks++) {
            const int k = t * K1_KB + ks * 16;
            unsigned a0 = f2bf2(*(const float2*)(xr0 + k));
            unsigned a1 = f2bf2(*(const float2*)(xr8 + k));
            unsigned a2 = f2bf2(*(const float2*)(xr0 + k + 8));
            unsigned a3 = f2bf2(*(const float2*)(xr8 + k + 8));
            #pragma unroll
            for (int nt = 0; nt < 8; nt++) {
                const char* wrow = wB + (nt * 8 + (lane >> 2)) * WROW_B
                                      + ks * 32 + 4 * (lane & 3);
                unsigned b0 = *(const unsigned*)(wrow);
                unsigned b1 = *(const unsigned*)(wrow + 16);
                mma16816(acc[nt], a0, a1, a2, a3, b0, b1);
            }
        }
        __syncthreads();
        buf ^= 1;
    }

    float* sc = (float*)dsm;                  // [128][68]
    {
        int r = 16 * wid + (lane >> 2);
        int cb = 2 * (lane & 3);
        #pragma unroll
        for (int nt = 0; nt < 8; nt++) {
            int c = 8 * nt + cb;
            sc[r * 68 + c]           = acc[nt][0];
            sc[r * 68 + c + 1]       = acc[nt][1];
            sc[(r + 8) * 68 + c]     = acc[nt][2];
            sc[(r + 8) * 68 + c + 1] = acc[nt][3];
        }
    }
    __syncthreads();

    if (tid < 128) {
        float sv[NCAND];
        int   si[NCAND];
        #pragma unroll
        for (int j = 0; j < NCAND; j++) { sv[j] = -INFINITY; si[j] = 0; }
        #pragma unroll
        for (int e = 0; e < NE; e++) {
            float cs = sc[tid * 68 + e] + s_bias[e];
            int ci = e;
            #pragma unroll
            for (int j = 0; j < NCAND; j++) {
                if (cs > sv[j]) {
                    float tf = sv[j]; int ti = si[j];
                    sv[j] = cs; si[j] = ci; cs = tf; ci = ti;
                }
            }
        }
        // adaptive rescore width: candidates within NC_WIN of screen rank-2
        int nc = 2;
        float thr = sv[1] - NC_WIN;
        #pragma unroll
        for (int j = 2; j < NCAND; j++)
            if (sv[j] >= thr) nc = j + 1;

        int token = row0 + tid;
        unsigned lo = (unsigned)si[0] | ((unsigned)si[1] << 8) |
                      ((unsigned)si[2] << 16) | ((unsigned)si[3] << 24);
        unsigned hi = (unsigned)si[4] | ((unsigned)si[5] << 8) |
                      ((unsigned)si[6] << 16) | ((unsigned)si[7] << 24);
        *(uint2*)&g_cand[(size_t)token * NCAND] = make_uint2(lo, hi);
        g_ncand[token] = (unsigned char)nc;
    }
}

// ================= K2 v3: adaptive-width conflict-free exact rescore =================
// CTA: 512 threads, 64 tokens. Warp = 4 tokens (tt=lane>>3) x 8 K-sublanes (kk=lane&7).
#define K2_KB     64
#define K2_TILES  (D_MODEL / K2_KB)      // 64
#define K2_WROW   68

__global__ __launch_bounds__(512, 2)
void k2_exact(const float* __restrict__ X, const float* __restrict__ W,
              const float* __restrict__ b, float* __restrict__ out, int n_tokens)
{
    __shared__ float Ws[2][NE][K2_WROW];
    __shared__ float bs[NE];

    const int tid  = threadIdx.x;
    const int wid  = tid >> 5;          // 0..15
    const int lane = tid & 31;
    const int tt   = lane >> 3;         // token-in-warp
    const int kk   = lane & 7;          // K sublane
    const int tok0 = blockIdx.x * 64;
    const int token = tok0 + 4 * wid + tt;

    if (tid < NE) bs[tid] = b[tid];

    auto prefetch = [&](int t, int buf) {
        const int kb = t * K2_KB;
        unsigned base = s2u(&Ws[buf][0][0]);
        #pragma unroll
        for (int j = 0; j < 2; j++) {
            int idx = tid + j * 512;
            int e = idx >> 4;
            int q = idx & 15;
            cp16(base + ((unsigned)e * K2_WROW + (unsigned)q * 4) * 4,
                 W + (size_t)e * D_MODEL + kb + q * 4);
        }
        cp_commit();
    };

    // candidates (all 8 stored, sorted desc by screen score)
    uint2 cd = *(const uint2*)&g_cand[(size_t)token * NCAND];
    int e[NCAND];
    #pragma unroll
    for (int j = 0; j < 4; j++) e[j]     = (cd.x >> (8 * j)) & 63;
    #pragma unroll
    for (int j = 0; j < 4; j++) e[4 + j] = (cd.y >> (8 * j)) & 63;

    // warp-uniform rescore width
    unsigned nc = g_ncand[token];
    nc = max(nc, __shfl_xor_sync(0xFFFFFFFFu, nc, 8));
    nc = max(nc, __shfl_xor_sync(0xFFFFFFFFu, nc, 16));
    const int wnc = (int)nc;            // 2..8, uniform across warp

    float sum[NCAND], cmp[NCAND];
    #pragma unroll
    for (int j = 0; j < NCAND; j++) { sum[j] = 0.0f; cmp[j] = 0.0f; }

    const float* xrow = X + (size_t)token * D_MODEL;

    prefetch(0, 0);
    int buf = 0;

    for (int t = 0; t < K2_TILES; t++) {
        const bool has_next = (t + 1 < K2_TILES);
        if (has_next) prefetch(t + 1, buf ^ 1);
        cp_wait(has_next ? 1 : 0);
        __syncthreads();

        const int kb = t * K2_KB;
        float4 xa = *(const float4*)(xrow + kb + 4 * kk);
        float4 xb = *(const float4*)(xrow + kb + 32 + 4 * kk);

        #pragma unroll
        for (int j = 0; j < NCAND; j++) {
            if (j >= wnc) break;        // warp-uniform early exit
            const float* wr = &Ws[buf][e[j]][0];
            float4 wa = *(const float4*)(wr + 4 * kk);        // conflict-free
            float4 wb = *(const float4*)(wr + 32 + 4 * kk);
            float s = xa.x * wa.x;
            s = fmaf(xa.y, wa.y, s);
            s = fmaf(xa.z, wa.z, s);
            s = fmaf(xa.w, wa.w, s);
            s = fmaf(xb.x, wb.x, s);
            s = fmaf(xb.y, wb.y, s);
            s = fmaf(xb.z, wb.z, s);
            s = fmaf(xb.w, wb.w, s);
            // Kahan merge (rn intrinsics: no contraction/reassociation)
            float y  = __fsub_rn(s, cmp[j]);
            float s2 = __fadd_rn(sum[j], y);
            cmp[j] = __fsub_rn(__fsub_rn(s2, sum[j]), y);
            sum[j] = s2;
        }

        __syncthreads();
        buf ^= 1;
    }

    // compensated per-lane partials, reduce across 8 kk-lanes, select top-2
    float m1 = -INFINITY, m2 = -INFINITY;
    int   i1 = 0,         i2 = 0;
    #pragma unroll
    for (int j = 0; j < NCAND; j++) {
        if (j >= wnc) break;
        float s = __fadd_rn(sum[j], __fsub_rn(0.0f, cmp[j]));
        s = __fadd_rn(s, __shfl_xor_sync(0xFFFFFFFFu, s, 1));
        s = __fadd_rn(s, __shfl_xor_sync(0xFFFFFFFFu, s, 2));
        s = __fadd_rn(s, __shfl_xor_sync(0xFFFFFFFFu, s, 4));
        s = __fadd_rn(s, bs[e[j]]);
        if (s > m1 || (s == m1 && e[j] < i1)) {
            m2 = m1; i2 = i1; m1 = s; i1 = e[j];
        } else if (s > m2 || (s == m2 && e[j] < i2)) {
            m2 = s; i2 = e[j];
        }
    }

    if (kk == 0) {
        float e2v = expf(m2 - m1);
        float inv = 1.0f / (1.0f + e2v);

        out[(size_t)token * 2 + 0] = inv;
        out[(size_t)token * 2 + 1] = e2v * inv;
        size_t idx_base = (size_t)n_tokens * 2;
        out[idx_base + (size_t)token * 2 + 0] = (float)i1;
        out[idx_base + (size_t)token * 2 + 1] = (float)i2;
    }
}

// ================= launch =================
extern "C" void kernel_launch(void* const* d_in, const int* in_sizes, int n_in,
                              void* d_out, int out_size)
{
    const float* X = (const float*)d_in[0];
    const float* W = (const float*)d_in[1];
    const float* b = (const float*)d_in[2];
    float* out = (float*)d_out;

    int n_tokens = in_sizes[0] / D_MODEL;     // 32768

    cudaFuncSetAttribute(k1_approx,
                         cudaFuncAttributeMaxDynamicSharedMemorySize, K1_SMEM);

    k0_convert_w<<<256, 256>>>(W);
    k1_approx<<<n_tokens / 128, 256, K1_SMEM>>>(X, b, n_tokens);
    k2_exact<<<n_tokens / 64, 512>>>(X, W, b, out, n_tokens);
}

// round 8
// speedup vs baseline: 2.3014x; 1.2151x over previous
#include <cuda_runtime.h>
#include <cuda_bf16.h>
#include <math.h>
#include <stdint.h>

#define D_MODEL   4096
#define NE        64
#define NTOK_MAX  32768
#define TAU       1e-3f   // certification margin (~250 sigma of screen noise)

// ---------------- scratch (__device__ globals: allocation-free) ----------------
__device__ __align__(16) __nv_bfloat16 g_Whi[NE * D_MODEL];    // 512 KB
__device__ __align__(16) __nv_bfloat16 g_Wlo[NE * D_MODEL];    // 512 KB
__device__ int g_rescue[NTOK_MAX];
__device__ int g_count;

// ---------------- helpers ----------------
__device__ __forceinline__ unsigned s2u(const void* p) {
    return (unsigned)__cvta_generic_to_shared(p);
}
__device__ __forceinline__ void cp16(unsigned sdst, const void* g) {
    asm volatile("cp.async.cg.shared.global [%0], [%1], 16;\n" :: "r"(sdst), "l"(g));
}
__device__ __forceinline__ void cp_commit() { asm volatile("cp.async.commit_group;\n"); }
__device__ __forceinline__ void cp_wait(int n) {
    if (n == 0) asm volatile("cp.async.wait_group 0;\n");
    else        asm volatile("cp.async.wait_group 1;\n");
}
__device__ __forceinline__ unsigned f2bf2(float2 v) {
    __nv_bfloat162 p = __float22bfloat162_rn(v);
    return *(unsigned*)&p;
}
__device__ __forceinline__ float2 bf2f2(unsigned u) {
    return __bfloat1622float2(*(__nv_bfloat162*)&u);
}
__device__ __forceinline__ void mma16816(float c[4], unsigned a0, unsigned a1,
                                         unsigned a2, unsigned a3,
                                         unsigned b0, unsigned b1) {
    asm volatile(
        "mma.sync.aligned.m16n8k16.row.col.f32.bf16.bf16.f32 "
        "{%0,%1,%2,%3}, {%4,%5,%6,%7}, {%8,%9}, {%0,%1,%2,%3};"
        : "+f"(c[0]), "+f"(c[1]), "+f"(c[2]), "+f"(c[3])
        : "r"(a0), "r"(a1), "r"(a2), "r"(a3), "r"(b0), "r"(b1));
}

// ================= K0: W fp32 -> (bf16 hi, bf16 lo); zero rescue counter =================
__global__ void k0_convert_w(const float* __restrict__ W) {
    if (blockIdx.x == 0 && threadIdx.x == 0) g_count = 0;
    int g = blockIdx.x * blockDim.x + threadIdx.x;     // float4 index, 65536 total
    float4 v = *(const float4*)(W + (size_t)g * 4);
    unsigned h0 = f2bf2(make_float2(v.x, v.y));
    unsigned h1 = f2bf2(make_float2(v.z, v.w));
    float2 hf0 = bf2f2(h0), hf1 = bf2f2(h1);
    unsigned l0 = f2bf2(make_float2(v.x - hf0.x, v.y - hf0.y));
    unsigned l1 = f2bf2(make_float2(v.z - hf1.x, v.w - hf1.y));
    *(uint2*)&g_Whi[(size_t)g * 4] = make_uint2(h0, h1);
    *(uint2*)&g_Wlo[(size_t)g * 4] = make_uint2(l0, l1);
}

// ================= K1: split-bf16 (3-MMA) near-exact screen + direct output =================
// CTA: 128 tokens x 64 experts. K staged 128 wide; hi rows 0..63, lo rows 64..127.
#define K1_KB     128
#define K1_STAGES (D_MODEL / K1_KB)         // 32
#define WROW_BF   136                       // 128 bf16 + 8 pad -> 272 B row
#define WROW_B    (WROW_BF * 2)
#define WBUF_B    (128 * WROW_B)            // 34816 (hi 64 rows + lo 64 rows)
#define LO_OFF    (64 * WROW_B)             // 17408
#define K1_SMEM   (2 * WBUF_B)              // 69632

__global__ __launch_bounds__(256, 2)
void k1_screen(const float* __restrict__ X, const float* __restrict__ b,
               float* __restrict__ out, int n_tokens)
{
    extern __shared__ __align__(16) char dsm[];
    __shared__ float s_bias[NE];

    const int tid  = threadIdx.x;
    const int wid  = tid >> 5;
    const int lane = tid & 31;
    const int row0 = blockIdx.x * 128;

    if (tid < NE) s_bias[tid] = b[tid];

    // stage fetch: 128 rows x 16 granules(16B) = 2048, 8 per thread
    auto prefetch = [&](int t, int buf) {
        const int kb = t * K1_KB;
        unsigned base = s2u(dsm) + buf * WBUF_B;
        #pragma unroll
        for (int j = 0; j < 8; j++) {
            int idx = tid + j * 256;            // 0..2047
            int r = idx >> 4;                   // 0..127
            int q = idx & 15;                   // 16B granule
            const __nv_bfloat16* src =
                (r < 64 ? g_Whi + (size_t)r * D_MODEL
                        : g_Wlo + (size_t)(r - 64) * D_MODEL) + kb + q * 8;
            cp16(base + (unsigned)r * WROW_B + (unsigned)q * 16, src);
        }
        cp_commit();
    };

    const float* xr0 = X + (size_t)(row0 + 16 * wid + (lane >> 2)) * D_MODEL
                         + 2 * (lane & 3);
    const float* xr8 = xr0 + (size_t)8 * D_MODEL;

    float acc[8][4];
    #pragma unroll
    for (int nt = 0; nt < 8; nt++)
        #pragma unroll
        for (int j = 0; j < 4; j++) acc[nt][j] = 0.0f;

    prefetch(0, 0);
    int buf = 0;

    for (int t = 0; t < K1_STAGES; t++) {
        const bool has_next = (t + 1 < K1_STAGES);
        if (has_next) prefetch(t + 1, buf ^ 1);
        cp_wait(has_next ? 1 : 0);
        __syncthreads();

        const char* wB = dsm + buf * WBUF_B;

        #pragma unroll
        for (int ks = 0; ks < K1_KB / 16; ks++) {
            const int k = t * K1_KB + ks * 16;
            // A fragments: hi + lo splits of X
            float2 v00 = *(const float2*)(xr0 + k);
            float2 v10 = *(const float2*)(xr8 + k);
            float2 v01 = *(const float2*)(xr0 + k + 8);
            float2 v11 = *(const float2*)(xr8 + k + 8);
            unsigned a0h = f2bf2(v00), a1h = f2bf2(v10);
            unsigned a2h = f2bf2(v01), a3h = f2bf2(v11);
            float2 h0 = bf2f2(a0h), h1 = bf2f2(a1h), h2 = bf2f2(a2h), h3 = bf2f2(a3h);
            unsigned a0l = f2bf2(make_float2(v00.x - h0.x, v00.y - h0.y));
            unsigned a1l = f2bf2(make_float2(v10.x - h1.x, v10.y - h1.y));
            unsigned a2l = f2bf2(make_float2(v01.x - h2.x, v01.y - h2.y));
            unsigned a3l = f2bf2(make_float2(v11.x - h3.x, v11.y - h3.y));

            #pragma unroll
            for (int nt = 0; nt < 8; nt++) {
                const char* wrow = wB + (nt * 8 + (lane >> 2)) * WROW_B
                                      + ks * 32 + 4 * (lane & 3);
                unsigned b0h = *(const unsigned*)(wrow);
                unsigned b1h = *(const unsigned*)(wrow + 16);
                unsigned b0l = *(const unsigned*)(wrow + LO_OFF);
                unsigned b1l = *(const unsigned*)(wrow + LO_OFF + 16);
                mma16816(acc[nt], a0h, a1h, a2h, a3h, b0h, b1h);  // hi*hi
                mma16816(acc[nt], a0h, a1h, a2h, a3h, b0l, b1l);  // hi*lo
                mma16816(acc[nt], a0l, a1l, a2l, a3l, b0h, b1h);  // lo*hi
            }
        }
        __syncthreads();
        buf ^= 1;
    }

    // ---- scores to smem (alias W buffers) ----
    float* sc = (float*)dsm;                  // [128][68]
    {
        int r = 16 * wid + (lane >> 2);
        int cb = 2 * (lane & 3);
        #pragma unroll
        for (int nt = 0; nt < 8; nt++) {
            int c = 8 * nt + cb;
            sc[r * 68 + c]           = acc[nt][0];
            sc[r * 68 + c + 1]       = acc[nt][1];
            sc[(r + 8) * 68 + c]     = acc[nt][2];
            sc[(r + 8) * 68 + c + 1] = acc[nt][3];
        }
    }
    __syncthreads();

    // ---- top-3 scan, certify, write outputs; rescue uncertain tokens ----
    if (tid < 128) {
        float s1 = -INFINITY, s2 = -INFINITY, s3 = -INFINITY;
        int   i1 = 0,         i2 = 0;
        #pragma unroll
        for (int e = 0; e < NE; e++) {
            float s = sc[tid * 68 + e] + s_bias[e];
            if (s > s1) { s3 = s2; s2 = s1; i2 = i1; s1 = s; i1 = e; }
            else if (s > s2) { s3 = s2; s2 = s; i2 = e; }
            else if (s > s3) { s3 = s; }
        }
        int token = row0 + tid;

        float e2v = expf(s2 - s1);
        float inv = 1.0f / (1.0f + e2v);
        out[(size_t)token * 2 + 0] = inv;
        out[(size_t)token * 2 + 1] = e2v * inv;
        size_t idx_base = (size_t)n_tokens * 2;
        out[idx_base + (size_t)token * 2 + 0] = (float)i1;
        out[idx_base + (size_t)token * 2 + 1] = (float)i2;

        if ((s1 - s2 < TAU) || (s2 - s3 < TAU)) {
            int slot = atomicAdd(&g_count, 1);
            g_rescue[slot] = token;
        }
    }
}

// ================= K3: exact fp32 rescore over ALL 64 experts (rescued tokens) =================
__global__ __launch_bounds__(128, 8)
void k3_rescue(const float* __restrict__ X, const float* __restrict__ W,
               const float* __restrict__ b, float* __restrict__ out, int n_tokens)
{
    __shared__ float sc[NE];
    const int tid  = threadIdx.x;
    const int wid  = tid >> 5;          // 0..3 -> experts 16w..16w+15
    const int lane = tid & 31;
    const int cnt  = g_count;

    for (int it = blockIdx.x; it < cnt; it += gridDim.x) {
        const int token = g_rescue[it];
        const float* xr = X + (size_t)token * D_MODEL;

        float a[16];
        #pragma unroll
        for (int j = 0; j < 16; j++) a[j] = 0.0f;

        for (int s = 0; s < D_MODEL / 128; s++) {         // 32 steps
            float4 xq = *(const float4*)(xr + s * 128 + lane * 4);
            #pragma unroll
            for (int j = 0; j < 16; j++) {
                const float4 wq = *(const float4*)(W + (size_t)(wid * 16 + j) * D_MODEL
                                                     + s * 128 + lane * 4);
                a[j] = fmaf(xq.x, wq.x, a[j]);
                a[j] = fmaf(xq.y, wq.y, a[j]);
                a[j] = fmaf(xq.z, wq.z, a[j]);
                a[j] = fmaf(xq.w, wq.w, a[j]);
            }
        }
        #pragma unroll
        for (int j = 0; j < 16; j++) {
            float r = a[j];
            r = __fadd_rn(r, __shfl_xor_sync(0xFFFFFFFFu, r, 16));
            r = __fadd_rn(r, __shfl_xor_sync(0xFFFFFFFFu, r, 8));
            r = __fadd_rn(r, __shfl_xor_sync(0xFFFFFFFFu, r, 4));
            r = __fadd_rn(r, __shfl_xor_sync(0xFFFFFFFFu, r, 2));
            r = __fadd_rn(r, __shfl_xor_sync(0xFFFFFFFFu, r, 1));
            if (lane == 0) sc[wid * 16 + j] = __fadd_rn(r, b[wid * 16 + j]);
        }
        __syncthreads();

        if (tid == 0) {
            float m1 = -INFINITY, m2 = -INFINITY;
            int   i1 = 0,         i2 = 0;
            #pragma unroll
            for (int e = 0; e < NE; e++) {
                float s = sc[e];
                if (s > m1) { m2 = m1; i2 = i1; m1 = s; i1 = e; }
                else if (s > m2) { m2 = s; i2 = e; }
            }
            float e2v = expf(m2 - m1);
            float inv = 1.0f / (1.0f + e2v);
            out[(size_t)token * 2 + 0] = inv;
            out[(size_t)token * 2 + 1] = e2v * inv;
            size_t idx_base = (size_t)n_tokens * 2;
            out[idx_base + (size_t)token * 2 + 0] = (float)i1;
            out[idx_base + (size_t)token * 2 + 1] = (float)i2;
        }
        __syncthreads();
    }
}

// ================= launch =================
extern "C" void kernel_launch(void* const* d_in, const int* in_sizes, int n_in,
                              void* d_out, int out_size)
{
    const float* X = (const float*)d_in[0];   // [N, 4096]
    const float* W = (const float*)d_in[1];   // [64, 4096]
    const float* b = (const float*)d_in[2];   // [64]
    float* out = (float*)d_out;

    int n_tokens = in_sizes[0] / D_MODEL;     // 32768

    cudaFuncSetAttribute(k1_screen,
                         cudaFuncAttributeMaxDynamicSharedMemorySize, K1_SMEM);

    k0_convert_w<<<256, 256>>>(W);
    k1_screen<<<n_tokens / 128, 256, K1_SMEM>>>(X, b, out, n_tokens);
    k3_rescue<<<512, 128>>>(X, W, b, out, n_tokens);
}

// round 9
// speedup vs baseline: 2.3949x; 1.0406x over previous
#include <cuda_runtime.h>
#include <cuda_fp16.h>
#include <math.h>
#include <stdint.h>

#define D_MODEL   4096
#define NE        64
#define NTOK_MAX  32768
#define TAU       8e-3f   // certification margin (~13 sigma of fp16 screen noise)

// ---------------- scratch (__device__ globals: allocation-free) ----------------
__device__ __align__(16) __half g_Wh[NE * D_MODEL];    // 512 KB
__device__ int g_rescue[NTOK_MAX];
__device__ int g_count;

// ---------------- helpers ----------------
__device__ __forceinline__ unsigned s2u(const void* p) {
    return (unsigned)__cvta_generic_to_shared(p);
}
__device__ __forceinline__ void cp16(unsigned sdst, const void* g) {
    asm volatile("cp.async.cg.shared.global [%0], [%1], 16;\n" :: "r"(sdst), "l"(g));
}
__device__ __forceinline__ void cp_commit() { asm volatile("cp.async.commit_group;\n"); }
__device__ __forceinline__ void cp_wait(int n) {
    if (n == 0) asm volatile("cp.async.wait_group 0;\n");
    else        asm volatile("cp.async.wait_group 1;\n");
}
__device__ __forceinline__ unsigned f2h2(float2 v) {
    __half2 h = __float22half2_rn(v);
    return *(unsigned*)&h;
}
__device__ __forceinline__ void mma16816(float c[4], unsigned a0, unsigned a1,
                                         unsigned a2, unsigned a3,
                                         unsigned b0, unsigned b1) {
    asm volatile(
        "mma.sync.aligned.m16n8k16.row.col.f32.f16.f16.f32 "
        "{%0,%1,%2,%3}, {%4,%5,%6,%7}, {%8,%9}, {%0,%1,%2,%3};"
        : "+f"(c[0]), "+f"(c[1]), "+f"(c[2]), "+f"(c[3])
        : "r"(a0), "r"(a1), "r"(a2), "r"(a3), "r"(b0), "r"(b1));
}

// ================= K0: W fp32 -> fp16; zero rescue counter =================
__global__ void k0_convert_w(const float* __restrict__ W) {
    if (blockIdx.x == 0 && threadIdx.x == 0) g_count = 0;
    int g = blockIdx.x * blockDim.x + threadIdx.x;     // float4 index, 65536 total
    float4 v = *(const float4*)(W + (size_t)g * 4);
    unsigned p0 = f2h2(make_float2(v.x, v.y));
    unsigned p1 = f2h2(make_float2(v.z, v.w));
    *(uint2*)&g_Wh[(size_t)g * 4] = make_uint2(p0, p1);
}

// ================= K1: fp16 single-MMA screen + certify + direct output =================
// CTA: 128 tokens x 64 experts. (geometry proven in R6)
#define K1_KB     256
#define K1_STAGES (D_MODEL / K1_KB)         // 16
#define WROW_H    264                       // 256 fp16 + 8 pad
#define WROW_B    (WROW_H * 2)
#define WBUF_B    (NE * WROW_B)             // 33792
#define K1_SMEM   (2 * WBUF_B)              // 67584

__global__ __launch_bounds__(256, 2)
void k1_screen(const float* __restrict__ X, const float* __restrict__ b,
               float* __restrict__ out, int n_tokens)
{
    extern __shared__ __align__(16) char dsm[];
    __shared__ float s_bias[NE];

    const int tid  = threadIdx.x;
    const int wid  = tid >> 5;
    const int lane = tid & 31;
    const int row0 = blockIdx.x * 128;

    if (tid < NE) s_bias[tid] = b[tid];

    auto prefetch = [&](int t, int buf) {
        const int kb = t * K1_KB;
        unsigned base = s2u(dsm) + buf * WBUF_B;
        #pragma unroll
        for (int j = 0; j < 8; j++) {
            int idx = tid + j * 256;
            int e = idx >> 5;
            int q = idx & 31;
            cp16(base + (unsigned)e * WROW_B + (unsigned)q * 16,
                 g_Wh + (size_t)e * D_MODEL + kb + q * 8);
        }
        cp_commit();
    };

    const float* xr0 = X + (size_t)(row0 + 16 * wid + (lane >> 2)) * D_MODEL
                         + 2 * (lane & 3);
    const float* xr8 = xr0 + (size_t)8 * D_MODEL;

    float acc[8][4];
    #pragma unroll
    for (int nt = 0; nt < 8; nt++)
        #pragma unroll
        for (int j = 0; j < 4; j++) acc[nt][j] = 0.0f;

    prefetch(0, 0);
    int buf = 0;

    for (int t = 0; t < K1_STAGES; t++) {
        const bool has_next = (t + 1 < K1_STAGES);
        if (has_next) prefetch(t + 1, buf ^ 1);
        cp_wait(has_next ? 1 : 0);
        __syncthreads();

        const char* wB = dsm + buf * WBUF_B;

        #pragma unroll 4
        for (int ks = 0; ks < K1_KB / 16; ks++) {
            const int k = t * K1_KB + ks * 16;
            unsigned a0 = f2h2(*(const float2*)(xr0 + k));
            unsigned a1 = f2h2(*(const float2*)(xr8 + k));
            unsigned a2 = f2h2(*(const float2*)(xr0 + k + 8));
            unsigned a3 = f2h2(*(const float2*)(xr8 + k + 8));
            #pragma unroll
            for (int nt = 0; nt < 8; nt++) {
                const char* wrow = wB + (nt * 8 + (lane >> 2)) * WROW_B
                                      + ks * 32 + 4 * (lane & 3);
                unsigned b0 = *(const unsigned*)(wrow);
                unsigned b1 = *(const unsigned*)(wrow + 16);
                mma16816(acc[nt], a0, a1, a2, a3, b0, b1);
            }
        }
        __syncthreads();
        buf ^= 1;
    }

    // ---- scores to smem (alias W buffers) ----
    float* sc = (float*)dsm;                  // [128][68]
    {
        int r = 16 * wid + (lane >> 2);
        int cb = 2 * (lane & 3);
        #pragma unroll
        for (int nt = 0; nt < 8; nt++) {
            int c = 8 * nt + cb;
            sc[r * 68 + c]           = acc[nt][0];
            sc[r * 68 + c + 1]       = acc[nt][1];
            sc[(r + 8) * 68 + c]     = acc[nt][2];
            sc[(r + 8) * 68 + c + 1] = acc[nt][3];
        }
    }
    __syncthreads();

    // ---- top-3 scan, write outputs, rescue uncertified tokens ----
    if (tid < 128) {
        float s1 = -INFINITY, s2 = -INFINITY, s3 = -INFINITY;
        int   i1 = 0,         i2 = 0;
        #pragma unroll
        for (int e = 0; e < NE; e++) {
            float s = sc[tid * 68 + e] + s_bias[e];
            if (s > s1) { s3 = s2; s2 = s1; i2 = i1; s1 = s; i1 = e; }
            else if (s > s2) { s3 = s2; s2 = s; i2 = e; }
            else if (s > s3) { s3 = s; }
        }
        int token = row0 + tid;

        float e2v = expf(s2 - s1);
        float inv = 1.0f / (1.0f + e2v);
        out[(size_t)token * 2 + 0] = inv;
        out[(size_t)token * 2 + 1] = e2v * inv;
        size_t idx_base = (size_t)n_tokens * 2;
        out[idx_base + (size_t)token * 2 + 0] = (float)i1;
        out[idx_base + (size_t)token * 2 + 1] = (float)i2;

        if ((s1 - s2 < TAU) || (s2 - s3 < TAU)) {
            int slot = atomicAdd(&g_count, 1);
            g_rescue[slot] = token;
        }
    }
}

// ================= K3: exact fp32 full rescore, 16 rescued tokens per CTA =================
// 512 threads = 16 warps. warp (tb=wid>>2, eb=wid&3): tokens tb*4+tt, experts eb*16+j.
// Lane (tt=lane>>3, kk=lane&7). W staged 64x64-k fp32 tiles, conflict-free LDS (R6-proven).
#define K3_KB    64
#define K3_TILES (D_MODEL / K3_KB)      // 64
#define K3_WROW  68

__global__ __launch_bounds__(512, 1)
void k3_rescue(const float* __restrict__ X, const float* __restrict__ W,
               const float* __restrict__ b, float* __restrict__ out, int n_tokens)
{
    __shared__ float Ws[2][NE][K3_WROW];
    __shared__ float sc[16][68];
    __shared__ float bs[NE];
    __shared__ int   toks[16];

    const int tid  = threadIdx.x;
    const int wid  = tid >> 5;
    const int lane = tid & 31;
    const int tb   = wid >> 2;          // 0..3
    const int eb   = wid & 3;           // 0..3 -> experts eb*16..+15
    const int tt   = lane >> 3;         // 0..3
    const int kk   = lane & 7;          // 0..7

    const int cnt = g_count;
    const int nchunks = (cnt + 15) >> 4;
    if (tid < NE) bs[tid] = b[tid];

    auto prefetch = [&](int t, int buf) {
        const int kb = t * K3_KB;
        unsigned base = s2u(&Ws[buf][0][0]);
        #pragma unroll
        for (int j = 0; j < 2; j++) {
            int idx = tid + j * 512;            // 0..1023
            int e = idx >> 4;
            int q = idx & 15;
            cp16(base + ((unsigned)e * K3_WROW + (unsigned)q * 4) * 4,
                 W + (size_t)e * D_MODEL + kb + q * 4);
        }
        cp_commit();
    };

    for (int chunk = blockIdx.x; chunk < nchunks; chunk += gridDim.x) {
        if (tid < 16) {
            int s = chunk * 16 + tid;
            toks[tid] = g_rescue[s < cnt ? s : cnt - 1];
        }
        __syncthreads();

        const int token = toks[tb * 4 + tt];
        const float* xrow = X + (size_t)token * D_MODEL;

        float sum[16], cmp[16];
        #pragma unroll
        for (int j = 0; j < 16; j++) { sum[j] = 0.0f; cmp[j] = 0.0f; }

        prefetch(0, 0);
        int buf = 0;

        for (int t = 0; t < K3_TILES; t++) {
            const bool has_next = (t + 1 < K3_TILES);
            if (has_next) prefetch(t + 1, buf ^ 1);
            cp_wait(has_next ? 1 : 0);
            __syncthreads();

            const int kb = t * K3_KB;
            float4 xa = *(const float4*)(xrow + kb + 4 * kk);
            float4 xb = *(const float4*)(xrow + kb + 32 + 4 * kk);

            #pragma unroll
            for (int j = 0; j < 16; j++) {
                const float* wr = &Ws[buf][eb * 16 + j][0];
                float4 wa = *(const float4*)(wr + 4 * kk);        // row-constant phase
                float4 wb = *(const float4*)(wr + 32 + 4 * kk);
                float s = xa.x * wa.x;
                s = fmaf(xa.y, wa.y, s);
                s = fmaf(xa.z, wa.z, s);
                s = fmaf(xa.w, wa.w, s);
                s = fmaf(xb.x, wb.x, s);
                s = fmaf(xb.y, wb.y, s);
                s = fmaf(xb.z, wb.z, s);
                s = fmaf(xb.w, wb.w, s);
                // Kahan merge (rn intrinsics)
                float y  = __fsub_rn(s, cmp[j]);
                float s2 = __fadd_rn(sum[j], y);
                cmp[j] = __fsub_rn(__fsub_rn(s2, sum[j]), y);
                sum[j] = s2;
            }

            __syncthreads();
            buf ^= 1;
        }

        // reduce across 8 kk-lanes; kk==0 writes 16 exact scores
        #pragma unroll
        for (int j = 0; j < 16; j++) {
            float s = __fadd_rn(sum[j], __fsub_rn(0.0f, cmp[j]));
            s = __fadd_rn(s, __shfl_xor_sync(0xFFFFFFFFu, s, 1));
            s = __fadd_rn(s, __shfl_xor_sync(0xFFFFFFFFu, s, 2));
            s = __fadd_rn(s, __shfl_xor_sync(0xFFFFFFFFu, s, 4));
            if (kk == 0) sc[tb * 4 + tt][eb * 16 + j] = __fadd_rn(s, bs[eb * 16 + j]);
        }
        __syncthreads();

        if (tid < 16) {
            int token2 = toks[tid];
            float m1 = -INFINITY, m2 = -INFINITY;
            int   i1 = 0,         i2 = 0;
            #pragma unroll
            for (int e = 0; e < NE; e++) {
                float s = sc[tid][e];
                if (s > m1) { m2 = m1; i2 = i1; m1 = s; i1 = e; }
                else if (s > m2) { m2 = s; i2 = e; }
            }
            float e2v = expf(m2 - m1);
            float inv = 1.0f / (1.0f + e2v);
            out[(size_t)token2 * 2 + 0] = inv;
            out[(size_t)token2 * 2 + 1] = e2v * inv;
            size_t idx_base = (size_t)n_tokens * 2;
            out[idx_base + (size_t)token2 * 2 + 0] = (float)i1;
            out[idx_base + (size_t)token2 * 2 + 1] = (float)i2;
        }
        __syncthreads();
    }
}

// ================= launch =================
extern "C" void kernel_launch(void* const* d_in, const int* in_sizes, int n_in,
                              void* d_out, int out_size)
{
    const float* X = (const float*)d_in[0];   // [N, 4096]
    const float* W = (const float*)d_in[1];   // [64, 4096]
    const float* b = (const float*)d_in[2];   // [64]
    float* out = (float*)d_out;

    int n_tokens = in_sizes[0] / D_MODEL;     // 32768

    cudaFuncSetAttribute(k1_screen,
                         cudaFuncAttributeMaxDynamicSharedMemorySize, K1_SMEM);

    k0_convert_w<<<256, 256>>>(W);
    k1_screen<<<n_tokens / 128, 256, K1_SMEM>>>(X, b, out, n_tokens);
    k3_rescue<<<256, 512>>>(X, W, b, out, n_tokens);
}

// round 10
// speedup vs baseline: 3.0979x; 1.2935x over previous
#include <cuda_runtime.h>
#include <cuda_fp16.h>
#include <math.h>
#include <stdint.h>

#define D_MODEL   4096
#define NE        64
#define NTOK_MAX  32768
#define TAU       5e-3f   // certification margin (~12.5 sigma of fp16 screen noise)
#define WIN       5e-3f   // candidate-containment window for rescued tokens

// ---------------- scratch (__device__ globals: allocation-free) ----------------
// W permuted into HMMA B-fragment order:
// unit (e, ks2) -> 64B: [q:4][ksl:2][half:2] uint = half2( W[e][ksl*16+half*8+q*2], +1 )
__device__ __align__(16) uint4 g_Wp[NE * 128 * 4];        // 512 KB
__device__ unsigned g_rtok[NTOK_MAX];                     // token | nc<<20
__device__ uint2    g_rcand[NTOK_MAX];                    // 8 packed candidate ids
__device__ int      g_count;

// ---------------- helpers ----------------
__device__ __forceinline__ unsigned f2h2(float2 v) {
    __half2 h = __float22half2_rn(v);
    return *(unsigned*)&h;
}
__device__ __forceinline__ void mma16816(float c[4], unsigned a0, unsigned a1,
                                         unsigned a2, unsigned a3,
                                         unsigned b0, unsigned b1) {
    asm volatile(
        "mma.sync.aligned.m16n8k16.row.col.f32.f16.f16.f32 "
        "{%0,%1,%2,%3}, {%4,%5,%6,%7}, {%8,%9}, {%0,%1,%2,%3};"
        : "+f"(c[0]), "+f"(c[1]), "+f"(c[2]), "+f"(c[3])
        : "r"(a0), "r"(a1), "r"(a2), "r"(a3), "r"(b0), "r"(b1));
}

// ================= K0: permute W fp32 -> fragment-ordered fp16; zero counter =================
__global__ void k0_permute_w(const float* __restrict__ W) {
    if (blockIdx.x == 0 && threadIdx.x == 0) g_count = 0;
    int unit = blockIdx.x * blockDim.x + threadIdx.x;   // 0..8191 = (e, ks2)
    int e   = unit >> 7;
    int ks2 = unit & 127;
    const float* src = W + (size_t)e * D_MODEL + ks2 * 32;

    float s[32];
    #pragma unroll
    for (int i = 0; i < 8; i++) {
        float4 v = *(const float4*)(src + i * 4);
        s[i * 4 + 0] = v.x; s[i * 4 + 1] = v.y; s[i * 4 + 2] = v.z; s[i * 4 + 3] = v.w;
    }
    unsigned u[16];
    #pragma unroll
    for (int q = 0; q < 4; q++)
        #pragma unroll
        for (int ksl = 0; ksl < 2; ksl++)
            #pragma unroll
            for (int half = 0; half < 2; half++) {
                int kk = ksl * 16 + half * 8 + q * 2;
                u[q * 4 + ksl * 2 + half] = f2h2(make_float2(s[kk], s[kk + 1]));
            }
    uint4* dst = &g_Wp[unit * 4];
    #pragma unroll
    for (int i = 0; i < 4; i++)
        dst[i] = make_uint4(u[i * 4], u[i * 4 + 1], u[i * 4 + 2], u[i * 4 + 3]);
}

// ================= K1: fp16 MMA screen, no smem staging (W via L1 __ldg) =================
// CTA: 128 tokens x 64 experts; warp w -> tokens 16w..16w+15.
__global__ __launch_bounds__(256, 2)
void k1_screen(const float* __restrict__ X, const float* __restrict__ b,
               float* __restrict__ out, int n_tokens)
{
    __shared__ float sc[128 * 68];
    __shared__ float s_bias[NE];

    const int tid  = threadIdx.x;
    const int wid  = tid >> 5;
    const int lane = tid & 31;
    const int row0 = blockIdx.x * 128;
    const int q    = lane & 3;
    const int rsub = lane >> 2;         // 0..7

    if (tid < NE) s_bias[tid] = b[tid];

    const float* xr0 = X + (size_t)(row0 + 16 * wid + rsub) * D_MODEL + 2 * q;
    const float* xr8 = xr0 + (size_t)8 * D_MODEL;

    float acc[8][4];
    #pragma unroll
    for (int nt = 0; nt < 8; nt++)
        #pragma unroll
        for (int j = 0; j < 4; j++) acc[nt][j] = 0.0f;

    #pragma unroll 2
    for (int ks2 = 0; ks2 < 128; ks2++) {
        const int k = ks2 * 32;
        // A fragments for even ks (k..k+15) and odd ks (k+16..k+31); X streamed (evict-first)
        unsigned aE0 = f2h2(__ldcs((const float2*)(xr0 + k)));
        unsigned aE1 = f2h2(__ldcs((const float2*)(xr8 + k)));
        unsigned aE2 = f2h2(__ldcs((const float2*)(xr0 + k + 8)));
        unsigned aE3 = f2h2(__ldcs((const float2*)(xr8 + k + 8)));
        unsigned aO0 = f2h2(__ldcs((const float2*)(xr0 + k + 16)));
        unsigned aO1 = f2h2(__ldcs((const float2*)(xr8 + k + 16)));
        unsigned aO2 = f2h2(__ldcs((const float2*)(xr0 + k + 24)));
        unsigned aO3 = f2h2(__ldcs((const float2*)(xr8 + k + 24)));

        #pragma unroll
        for (int nt = 0; nt < 8; nt++) {
            // B fragments straight from permuted gmem (L1-resident, shared by all warps)
            uint4 bb = __ldg(&g_Wp[((nt * 8 + rsub) * 128 + ks2) * 4 + q]);
            mma16816(acc[nt], aE0, aE1, aE2, aE3, bb.x, bb.y);
            mma16816(acc[nt], aO0, aO1, aO2, aO3, bb.z, bb.w);
        }
    }

    // ---- scores to smem ----
    {
        int r = 16 * wid + rsub;
        int cb = 2 * q;
        #pragma unroll
        for (int nt = 0; nt < 8; nt++) {
            int c = 8 * nt + cb;
            sc[r * 68 + c]             = acc[nt][0];
            sc[r * 68 + c + 1]         = acc[nt][1];
            sc[(r + 8) * 68 + c]       = acc[nt][2];
            sc[(r + 8) * 68 + c + 1]   = acc[nt][3];
        }
    }
    __syncthreads();

    // ---- per-token top-8 scan, certify, write outputs, rescue ----
    if (tid < 128) {
        float sv[8];
        int   si[8];
        #pragma unroll
        for (int j = 0; j < 8; j++) { sv[j] = -INFINITY; si[j] = 0; }
        #pragma unroll
        for (int e = 0; e < NE; e++) {
            float cs = sc[tid * 68 + e] + s_bias[e];
            int ci = e;
            #pragma unroll
            for (int j = 0; j < 8; j++) {
                if (cs > sv[j]) {
                    float tf = sv[j]; int ti = si[j];
                    sv[j] = cs; si[j] = ci; cs = tf; ci = ti;
                }
            }
        }
        int token = row0 + tid;

        float e2v = expf(sv[1] - sv[0]);
        float inv = 1.0f / (1.0f + e2v);
        out[(size_t)token * 2 + 0] = inv;
        out[(size_t)token * 2 + 1] = e2v * inv;
        size_t idx_base = (size_t)n_tokens * 2;
        out[idx_base + (size_t)token * 2 + 0] = (float)si[0];
        out[idx_base + (size_t)token * 2 + 1] = (float)si[1];

        if ((sv[0] - sv[1] < TAU) || (sv[1] - sv[2] < TAU)) {
            // candidate window: everything within WIN of screen rank-2
            int nc = 2;
            float thr = sv[1] - WIN;
            #pragma unroll
            for (int j = 2; j < 8; j++)
                if (sv[j] >= thr) nc = j + 1;
            int slot = atomicAdd(&g_count, 1);
            g_rtok[slot] = (unsigned)token | ((unsigned)nc << 20);
            unsigned lo = (unsigned)si[0] | ((unsigned)si[1] << 8) |
                          ((unsigned)si[2] << 16) | ((unsigned)si[3] << 24);
            unsigned hi = (unsigned)si[4] | ((unsigned)si[5] << 8) |
                          ((unsigned)si[6] << 16) | ((unsigned)si[7] << 24);
            g_rcand[slot] = make_uint2(lo, hi);
        }
    }
}

// ================= K3: warp-per-token exact fp32 rescore of the candidate window =================
__global__ __launch_bounds__(256, 4)
void k3_rescue(const float* __restrict__ X, const float* __restrict__ W,
               const float* __restrict__ b, float* __restrict__ out, int n_tokens)
{
    const int lane   = threadIdx.x & 31;
    const int gw     = (blockIdx.x * blockDim.x + threadIdx.x) >> 5;
    const int nwarps = (gridDim.x * blockDim.x) >> 5;
    const int cnt    = g_count;

    for (int it = gw; it < cnt; it += nwarps) {
        unsigned tv = g_rtok[it];
        const int token = tv & 0xFFFFF;
        const int nc    = tv >> 20;
        uint2 cd = g_rcand[it];
        int e[8];
        #pragma unroll
        for (int j = 0; j < 4; j++) e[j]     = (cd.x >> (8 * j)) & 63;
        #pragma unroll
        for (int j = 0; j < 4; j++) e[4 + j] = (cd.y >> (8 * j)) & 63;

        const float* xrow = X + (size_t)token * D_MODEL;

        float sum[8], cmp[8];
        #pragma unroll
        for (int j = 0; j < 8; j++) { sum[j] = 0.0f; cmp[j] = 0.0f; }

        for (int st = 0; st < D_MODEL / 128; st++) {       // 32 steps
            float4 xq = *(const float4*)(xrow + st * 128 + lane * 4);
            #pragma unroll
            for (int j = 0; j < 8; j++) {
                if (j >= nc) break;                        // warp-uniform
                float4 wq = __ldg((const float4*)(W + (size_t)e[j] * D_MODEL
                                                    + st * 128 + lane * 4));
                float s = xq.x * wq.x;
                s = fmaf(xq.y, wq.y, s);
                s = fmaf(xq.z, wq.z, s);
                s = fmaf(xq.w, wq.w, s);
                // Kahan merge (rn intrinsics: no contraction/reassociation)
                float y  = __fsub_rn(s, cmp[j]);
                float s2 = __fadd_rn(sum[j], y);
                cmp[j] = __fsub_rn(__fsub_rn(s2, sum[j]), y);
                sum[j] = s2;
            }
        }

        float m1 = -INFINITY, m2 = -INFINITY;
        int   i1 = 0,         i2 = 0;
        #pragma unroll
        for (int j = 0; j < 8; j++) {
            if (j >= nc) break;
            float s = __fadd_rn(sum[j], __fsub_rn(0.0f, cmp[j]));
            s = __fadd_rn(s, __shfl_xor_sync(0xFFFFFFFFu, s, 1));
            s = __fadd_rn(s, __shfl_xor_sync(0xFFFFFFFFu, s, 2));
            s = __fadd_rn(s, __shfl_xor_sync(0xFFFFFFFFu, s, 4));
            s = __fadd_rn(s, __shfl_xor_sync(0xFFFFFFFFu, s, 8));
            s = __fadd_rn(s, __shfl_xor_sync(0xFFFFFFFFu, s, 16));
            s = __fadd_rn(s, b[e[j]]);
            if (s > m1 || (s == m1 && e[j] < i1)) {
                m2 = m1; i2 = i1; m1 = s; i1 = e[j];
            } else if (s > m2 || (s == m2 && e[j] < i2)) {
                m2 = s; i2 = e[j];
            }
        }

        if (lane == 0) {
            float e2v = expf(m2 - m1);
            float inv = 1.0f / (1.0f + e2v);
            out[(size_t)token * 2 + 0] = inv;
            out[(size_t)token * 2 + 1] = e2v * inv;
            size_t idx_base = (size_t)n_tokens * 2;
            out[idx_base + (size_t)token * 2 + 0] = (float)i1;
            out[idx_base + (size_t)token * 2 + 1] = (float)i2;
        }
    }
}

// ================= launch =================
extern "C" void kernel_launch(void* const* d_in, const int* in_sizes, int n_in,
                              void* d_out, int out_size)
{
    const float* X = (const float*)d_in[0];   // [N, 4096]
    const float* W = (const float*)d_in[1];   // [64, 4096]
    const float* b = (const float*)d_in[2];   // [64]
    float* out = (float*)d_out;

    int n_tokens = in_sizes[0] / D_MODEL;     // 32768

    k0_permute_w<<<32, 256>>>(W);
    k1_screen<<<n_tokens / 128, 256>>>(X, b, out, n_tokens);
    k3_rescue<<<296, 256>>>(X, W, b, out, n_tokens);
}

// round 11
// speedup vs baseline: 3.6315x; 1.1722x over previous
#include <cuda_runtime.h>
#include <cuda_fp16.h>
#include <math.h>
#include <stdint.h>

#define D_MODEL   4096
#define NE        64
#define NTOK_MAX  32768
#define TAU       5e-3f   // certification margin (~12.5 sigma of fp16 screen noise)
#define WIN       5e-3f   // candidate-containment window for rescued tokens

// ---------------- scratch (__device__ globals: allocation-free) ----------------
// W permuted into warp-contiguous HMMA B-fragment blocks:
// block (nt, ks2) = 512B; lane l = rsub*4+q (expert e = nt*8+rsub) holds uint4 =
//   { half2(W[e][32ks2+2q],+1), half2(W[e][32ks2+8+2q],+1),
//     half2(W[e][32ks2+16+2q],+1), half2(W[e][32ks2+24+2q],+1) }
__device__ __align__(16) uint4 g_Wp[NE * 128 * 4];        // 512 KB
__device__ unsigned g_rtok[NTOK_MAX];                     // token | nc<<20
__device__ uint2    g_rcand[NTOK_MAX];                    // 8 packed candidate ids
__device__ int      g_count;

// ---------------- helpers ----------------
__device__ __forceinline__ unsigned f2h2(float a, float bb) {
    __half2 h = __float22half2_rn(make_float2(a, bb));
    return *(unsigned*)&h;
}
__device__ __forceinline__ void mma16816(float c[4], unsigned a0, unsigned a1,
                                         unsigned a2, unsigned a3,
                                         unsigned b0, unsigned b1) {
    asm volatile(
        "mma.sync.aligned.m16n8k16.row.col.f32.f16.f16.f32 "
        "{%0,%1,%2,%3}, {%4,%5,%6,%7}, {%8,%9}, {%0,%1,%2,%3};"
        : "+f"(c[0]), "+f"(c[1]), "+f"(c[2]), "+f"(c[3])
        : "r"(a0), "r"(a1), "r"(a2), "r"(a3), "r"(b0), "r"(b1));
}

// ================= K0: permute W fp32 -> warp-contiguous fragment fp16 =================
__global__ void k0_permute_w(const float* __restrict__ W) {
    if (blockIdx.x == 0 && threadIdx.x == 0) g_count = 0;
    int unit = blockIdx.x * blockDim.x + threadIdx.x;   // 0..8191 = (e, ks2)
    int e   = unit >> 7;
    int ks2 = unit & 127;
    int nt  = e >> 3;
    int rsub = e & 7;
    const float* src = W + (size_t)e * D_MODEL + ks2 * 32;

    float s[32];
    #pragma unroll
    for (int i = 0; i < 8; i++) {
        float4 v = *(const float4*)(src + i * 4);
        s[i * 4 + 0] = v.x; s[i * 4 + 1] = v.y; s[i * 4 + 2] = v.z; s[i * 4 + 3] = v.w;
    }
    // lane q holds { (2q), (8+2q), (16+2q), (24+2q) } column pairs
    uint4* dst = &g_Wp[((nt * 128 + ks2) * 8 + rsub) * 4];   // = base + rsub*4 uint4
    #pragma unroll
    for (int q = 0; q < 4; q++) {
        uint4 u;
        u.x = f2h2(s[2 * q],      s[2 * q + 1]);
        u.y = f2h2(s[8 + 2 * q],  s[8 + 2 * q + 1]);
        u.z = f2h2(s[16 + 2 * q], s[16 + 2 * q + 1]);
        u.w = f2h2(s[24 + 2 * q], s[24 + 2 * q + 1]);
        dst[q] = u;
    }
}

// ================= K1: fp16 MMA screen, shuffle-built A frags, contiguous W =================
// CTA: 128 tokens x 64 experts; warp w -> tokens 16w..16w+15. (R10-proven geometry)
__global__ __launch_bounds__(256, 2)
void k1_screen(const float* __restrict__ X, const float* __restrict__ b,
               float* __restrict__ out, int n_tokens)
{
    __shared__ float sc[128 * 68];
    __shared__ float s_bias[NE];

    const int tid  = threadIdx.x;
    const int wid  = tid >> 5;
    const int lane = tid & 31;
    const int row0 = blockIdx.x * 128;
    const int q    = lane & 3;
    const int rsub = lane >> 2;              // 0..7
    const int srcA = (lane & ~3) | ((lane >> 1) & 1);   // base + (q>>1)
    const bool hiP = (lane & 1);                         // pair parity

    if (tid < NE) s_bias[tid] = b[tid];

    // own-row pointers: row rsub (m0) and rsub+8 (m1), 16B chunk q
    const float* xr0 = X + (size_t)(row0 + 16 * wid + rsub) * D_MODEL + 4 * q;
    const float* xr8 = xr0 + (size_t)8 * D_MODEL;

    float acc[8][4];
    #pragma unroll
    for (int nt = 0; nt < 8; nt++)
        #pragma unroll
        for (int j = 0; j < 4; j++) acc[nt][j] = 0.0f;

    // software pipeline: preload iteration 0
    float4 L0 = __ldcs((const float4*)(xr0));
    float4 L1 = __ldcs((const float4*)(xr0 + 16));
    float4 L2 = __ldcs((const float4*)(xr8));
    float4 L3 = __ldcs((const float4*)(xr8 + 16));

    for (int ks2 = 0; ks2 < 128; ks2++) {
        // prefetch next iteration's A data
        float4 N0, N1, N2, N3;
        if (ks2 < 127) {
            const int kn = (ks2 + 1) * 32;
            N0 = __ldcs((const float4*)(xr0 + kn));
            N1 = __ldcs((const float4*)(xr0 + kn + 16));
            N2 = __ldcs((const float4*)(xr8 + kn));
            N3 = __ldcs((const float4*)(xr8 + kn + 16));
        }

        // pack own pairs to half2
        unsigned h00 = f2h2(L0.x, L0.y), h01 = f2h2(L0.z, L0.w);
        unsigned h10 = f2h2(L1.x, L1.y), h11 = f2h2(L1.z, L1.w);
        unsigned h20 = f2h2(L2.x, L2.y), h21 = f2h2(L2.z, L2.w);
        unsigned h30 = f2h2(L3.x, L3.y), h31 = f2h2(L3.z, L3.w);

        // build fragments via shuffle: consumer (rsub,q) <- source lane srcA (+2)
        unsigned u0, u1;
        u0 = __shfl_sync(0xFFFFFFFFu, h00, srcA);
        u1 = __shfl_sync(0xFFFFFFFFu, h01, srcA);
        unsigned aE0 = hiP ? u1 : u0;
        u0 = __shfl_sync(0xFFFFFFFFu, h00, srcA + 2);
        u1 = __shfl_sync(0xFFFFFFFFu, h01, srcA + 2);
        unsigned aE2 = hiP ? u1 : u0;
        u0 = __shfl_sync(0xFFFFFFFFu, h20, srcA);
        u1 = __shfl_sync(0xFFFFFFFFu, h21, srcA);
        unsigned aE1 = hiP ? u1 : u0;
        u0 = __shfl_sync(0xFFFFFFFFu, h20, srcA + 2);
        u1 = __shfl_sync(0xFFFFFFFFu, h21, srcA + 2);
        unsigned aE3 = hiP ? u1 : u0;
        u0 = __shfl_sync(0xFFFFFFFFu, h10, srcA);
        u1 = __shfl_sync(0xFFFFFFFFu, h11, srcA);
        unsigned aO0 = hiP ? u1 : u0;
        u0 = __shfl_sync(0xFFFFFFFFu, h10, srcA + 2);
        u1 = __shfl_sync(0xFFFFFFFFu, h11, srcA + 2);
        unsigned aO2 = hiP ? u1 : u0;
        u0 = __shfl_sync(0xFFFFFFFFu, h30, srcA);
        u1 = __shfl_sync(0xFFFFFFFFu, h31, srcA);
        unsigned aO1 = hiP ? u1 : u0;
        u0 = __shfl_sync(0xFFFFFFFFu, h30, srcA + 2);
        u1 = __shfl_sync(0xFFFFFFFFu, h31, srcA + 2);
        unsigned aO3 = hiP ? u1 : u0;

        #pragma unroll
        for (int nt = 0; nt < 8; nt++) {
            // one coalesced 512B block per (nt, ks2): lane reads its own uint4
            uint4 bb = __ldg(&g_Wp[((nt * 128 + ks2) * 8) * 4 + lane]);
            mma16816(acc[nt], aE0, aE1, aE2, aE3, bb.x, bb.y);
            mma16816(acc[nt], aO0, aO1, aO2, aO3, bb.z, bb.w);
        }

        L0 = N0; L1 = N1; L2 = N2; L3 = N3;
    }

    // ---- scores to smem ----
    {
        int r = 16 * wid + rsub;
        int cb = 2 * q;
        #pragma unroll
        for (int nt = 0; nt < 8; nt++) {
            int c = 8 * nt + cb;
            sc[r * 68 + c]             = acc[nt][0];
            sc[r * 68 + c + 1]         = acc[nt][1];
            sc[(r + 8) * 68 + c]       = acc[nt][2];
            sc[(r + 8) * 68 + c + 1]   = acc[nt][3];
        }
    }
    __syncthreads();

    // ---- per-token top-8 scan, certify, write outputs, rescue ----
    if (tid < 128) {
        float sv[8];
        int   si[8];
        #pragma unroll
        for (int j = 0; j < 8; j++) { sv[j] = -INFINITY; si[j] = 0; }
        #pragma unroll
        for (int e = 0; e < NE; e++) {
            float cs = sc[tid * 68 + e] + s_bias[e];
            int ci = e;
            #pragma unroll
            for (int j = 0; j < 8; j++) {
                if (cs > sv[j]) {
                    float tf = sv[j]; int ti = si[j];
                    sv[j] = cs; si[j] = ci; cs = tf; ci = ti;
                }
            }
        }
        int token = row0 + tid;

        float e2v = expf(sv[1] - sv[0]);
        float inv = 1.0f / (1.0f + e2v);
        out[(size_t)token * 2 + 0] = inv;
        out[(size_t)token * 2 + 1] = e2v * inv;
        size_t idx_base = (size_t)n_tokens * 2;
        out[idx_base + (size_t)token * 2 + 0] = (float)si[0];
        out[idx_base + (size_t)token * 2 + 1] = (float)si[1];

        if ((sv[0] - sv[1] < TAU) || (sv[1] - sv[2] < TAU)) {
            int nc = 2;
            float thr = sv[1] - WIN;
            #pragma unroll
            for (int j = 2; j < 8; j++)
                if (sv[j] >= thr) nc = j + 1;
            int slot = atomicAdd(&g_count, 1);
            g_rtok[slot] = (unsigned)token | ((unsigned)nc << 20);
            unsigned lo = (unsigned)si[0] | ((unsigned)si[1] << 8) |
                          ((unsigned)si[2] << 16) | ((unsigned)si[3] << 24);
            unsigned hi = (unsigned)si[4] | ((unsigned)si[5] << 8) |
                          ((unsigned)si[6] << 16) | ((unsigned)si[7] << 24);
            g_rcand[slot] = make_uint2(lo, hi);
        }
    }
}

// ================= K3: warp-per-token exact fp32 rescore of the candidate window =================
__global__ __launch_bounds__(256, 4)
void k3_rescue(const float* __restrict__ X, const float* __restrict__ W,
               const float* __restrict__ b, float* __restrict__ out, int n_tokens)
{
    const int lane   = threadIdx.x & 31;
    const int gw     = (blockIdx.x * blockDim.x + threadIdx.x) >> 5;
    const int nwarps = (gridDim.x * blockDim.x) >> 5;
    const int cnt    = g_count;

    for (int it = gw; it < cnt; it += nwarps) {
        unsigned tv = g_rtok[it];
        const int token = tv & 0xFFFFF;
        const int nc    = tv >> 20;
        uint2 cd = g_rcand[it];
        int e[8];
        #pragma unroll
        for (int j = 0; j < 4; j++) e[j]     = (cd.x >> (8 * j)) & 63;
        #pragma unroll
        for (int j = 0; j < 4; j++) e[4 + j] = (cd.y >> (8 * j)) & 63;

        const float* xrow = X + (size_t)token * D_MODEL;

        float sum[8], cmp[8];
        #pragma unroll
        for (int j = 0; j < 8; j++) { sum[j] = 0.0f; cmp[j] = 0.0f; }

        for (int st = 0; st < D_MODEL / 128; st++) {       // 32 steps
            float4 xq = *(const float4*)(xrow + st * 128 + lane * 4);
            #pragma unroll
            for (int j = 0; j < 8; j++) {
                if (j >= nc) break;                        // warp-uniform
                float4 wq = __ldg((const float4*)(W + (size_t)e[j] * D_MODEL
                                                    + st * 128 + lane * 4));
                float s = xq.x * wq.x;
                s = fmaf(xq.y, wq.y, s);
                s = fmaf(xq.z, wq.z, s);
                s = fmaf(xq.w, wq.w, s);
                // Kahan merge (rn intrinsics: no contraction/reassociation)
                float y  = __fsub_rn(s, cmp[j]);
                float s2 = __fadd_rn(sum[j], y);
                cmp[j] = __fsub_rn(__fsub_rn(s2, sum[j]), y);
                sum[j] = s2;
            }
        }

        float m1 = -INFINITY, m2 = -INFINITY;
        int   i1 = 0,         i2 = 0;
        #pragma unroll
        for (int j = 0; j < 8; j++) {
            if (j >= nc) break;
            float s = __fadd_rn(sum[j], __fsub_rn(0.0f, cmp[j]));
            s = __fadd_rn(s, __shfl_xor_sync(0xFFFFFFFFu, s, 1));
            s = __fadd_rn(s, __shfl_xor_sync(0xFFFFFFFFu, s, 2));
            s = __fadd_rn(s, __shfl_xor_sync(0xFFFFFFFFu, s, 4));
            s = __fadd_rn(s, __shfl_xor_sync(0xFFFFFFFFu, s, 8));
            s = __fadd_rn(s, __shfl_xor_sync(0xFFFFFFFFu, s, 16));
            s = __fadd_rn(s, b[e[j]]);
            if (s > m1 || (s == m1 && e[j] < i1)) {
                m2 = m1; i2 = i1; m1 = s; i1 = e[j];
            } else if (s > m2 || (s == m2 && e[j] < i2)) {
                m2 = s; i2 = e[j];
            }
        }

        if (lane == 0) {
            float e2v = expf(m2 - m1);
            float inv = 1.0f / (1.0f + e2v);
            out[(size_t)token * 2 + 0] = inv;
            out[(size_t)token * 2 + 1] = e2v * inv;
            size_t idx_base = (size_t)n_tokens * 2;
            out[idx_base + (size_t)token * 2 + 0] = (float)i1;
            out[idx_base + (size_t)token * 2 + 1] = (float)i2;
        }
    }
}

// ================= launch =================
extern "C" void kernel_launch(void* const* d_in, const int* in_sizes, int n_in,
                              void* d_out, int out_size)
{
    const float* X = (const float*)d_in[0];   // [N, 4096]
    const float* W = (const float*)d_in[1];   // [64, 4096]
    const float* b = (const float*)d_in[2];   // [64]
    float* out = (float*)d_out;

    int n_tokens = in_sizes[0] / D_MODEL;     // 32768

    k0_permute_w<<<32, 256>>>(W);
    k1_screen<<<n_tokens / 128, 256>>>(X, b, out, n_tokens);
    k3_rescue<<<296, 256>>>(X, W, b, out, n_tokens);
}

// round 12
// speedup vs baseline: 3.9724x; 1.0939x over previous
#include <cuda_runtime.h>
#include <cuda_fp16.h>
#include <math.h>
#include <stdint.h>

#define D_MODEL   4096
#define NE        64
#define NTOK_MAX  32768
#define TAU       5e-3f   // certification margin (~12.5 sigma of fp16 screen noise)
#define WIN       5e-3f   // candidate-containment window for rescued tokens

// ---------------- scratch (__device__ globals: allocation-free) ----------------
// W permuted into warp-contiguous HMMA B-fragment blocks (R11-proven layout):
// block (nt, ks2) = 512B; lane l = rsub*4+q (expert e = nt*8+rsub) holds uint4 =
//   { half2(W[e][32ks2+2q],+1), half2(W[e][32ks2+8+2q],+1),
//     half2(W[e][32ks2+16+2q],+1), half2(W[e][32ks2+24+2q],+1) }
__device__ __align__(16) uint4 g_Wp[NE * 128 * 4];        // 512 KB
__device__ unsigned g_rtok[NTOK_MAX];                     // token | nc<<20
__device__ uint2    g_rcand[NTOK_MAX];                    // 8 packed candidate ids
__device__ int      g_count;

// ---------------- helpers ----------------
__device__ __forceinline__ unsigned f2h2(float a, float bb) {
    __half2 h = __float22half2_rn(make_float2(a, bb));
    return *(unsigned*)&h;
}
__device__ __forceinline__ void mma16816(float c[4], unsigned a0, unsigned a1,
                                         unsigned a2, unsigned a3,
                                         unsigned b0, unsigned b1) {
    asm volatile(
        "mma.sync.aligned.m16n8k16.row.col.f32.f16.f16.f32 "
        "{%0,%1,%2,%3}, {%4,%5,%6,%7}, {%8,%9}, {%0,%1,%2,%3};"
        : "+f"(c[0]), "+f"(c[1]), "+f"(c[2]), "+f"(c[3])
        : "r"(a0), "r"(a1), "r"(a2), "r"(a3), "r"(b0), "r"(b1));
}

// ================= K0: permute W fp32 -> warp-contiguous fragment fp16 =================
__global__ void k0_permute_w(const float* __restrict__ W) {
    if (blockIdx.x == 0 && threadIdx.x == 0) g_count = 0;
    int unit = blockIdx.x * blockDim.x + threadIdx.x;   // 0..8191 = (e, ks2)
    int e   = unit >> 7;
    int ks2 = unit & 127;
    int nt  = e >> 3;
    int rsub = e & 7;
    const float* src = W + (size_t)e * D_MODEL + ks2 * 32;

    float s[32];
    #pragma unroll
    for (int i = 0; i < 8; i++) {
        float4 v = *(const float4*)(src + i * 4);
        s[i * 4 + 0] = v.x; s[i * 4 + 1] = v.y; s[i * 4 + 2] = v.z; s[i * 4 + 3] = v.w;
    }
    uint4* dst = &g_Wp[((nt * 128 + ks2) * 8 + rsub) * 4];
    #pragma unroll
    for (int q = 0; q < 4; q++) {
        uint4 u;
        u.x = f2h2(s[2 * q],      s[2 * q + 1]);
        u.y = f2h2(s[8 + 2 * q],  s[8 + 2 * q + 1]);
        u.z = f2h2(s[16 + 2 * q], s[16 + 2 * q + 1]);
        u.w = f2h2(s[24 + 2 * q], s[24 + 2 * q + 1]);
        dst[q] = u;
    }
}

// ================= K1: fp16 MMA screen, 32 tokens/warp (2 m16 blocks) =================
// CTA: 128 tokens, 4 warps; warp w -> tokens 32w..32w+31. A mapping = R11-proven.
__global__ __launch_bounds__(128, 2)
void k1_screen(const float* __restrict__ X, const float* __restrict__ b,
               float* __restrict__ out, int n_tokens)
{
    __shared__ float sc[128 * 68];
    __shared__ float s_bias[NE];

    const int tid  = threadIdx.x;
    const int wid  = tid >> 5;               // 0..3
    const int lane = tid & 31;
    const int row0 = blockIdx.x * 128;
    const int q    = lane & 3;
    const int rsub = lane >> 2;              // 0..7
    const int srcA = (lane & ~3) | ((lane >> 1) & 1);   // base + (q>>1)
    const bool hiP = (lane & 1);

    if (tid < NE) s_bias[tid] = b[tid];

    // rows: block0 = {rsub, rsub+8}, block1 = {rsub+16, rsub+24} within 32w..32w+31
    const float* xr0  = X + (size_t)(row0 + 32 * wid + rsub) * D_MODEL + 4 * q;
    const float* xr8  = xr0 + (size_t)8  * D_MODEL;
    const float* xr16 = xr0 + (size_t)16 * D_MODEL;
    const float* xr24 = xr0 + (size_t)24 * D_MODEL;

    float acc0[8][4], acc1[8][4];
    #pragma unroll
    for (int nt = 0; nt < 8; nt++)
        #pragma unroll
        for (int j = 0; j < 4; j++) { acc0[nt][j] = 0.0f; acc1[nt][j] = 0.0f; }

    for (int ks2 = 0; ks2 < 128; ks2++) {
        const int k = ks2 * 32;
        // 8 independent A loads (evict-first X stream)
        float4 L0 = __ldcs((const float4*)(xr0  + k));
        float4 L1 = __ldcs((const float4*)(xr0  + k + 16));
        float4 L2 = __ldcs((const float4*)(xr8  + k));
        float4 L3 = __ldcs((const float4*)(xr8  + k + 16));
        float4 L4 = __ldcs((const float4*)(xr16 + k));
        float4 L5 = __ldcs((const float4*)(xr16 + k + 16));
        float4 L6 = __ldcs((const float4*)(xr24 + k));
        float4 L7 = __ldcs((const float4*)(xr24 + k + 16));

        // pack own pairs to half2 (R11-proven mapping per block)
        unsigned h00 = f2h2(L0.x, L0.y), h01 = f2h2(L0.z, L0.w);
        unsigned h10 = f2h2(L1.x, L1.y), h11 = f2h2(L1.z, L1.w);
        unsigned h20 = f2h2(L2.x, L2.y), h21 = f2h2(L2.z, L2.w);
        unsigned h30 = f2h2(L3.x, L3.y), h31 = f2h2(L3.z, L3.w);
        unsigned h40 = f2h2(L4.x, L4.y), h41 = f2h2(L4.z, L4.w);
        unsigned h50 = f2h2(L5.x, L5.y), h51 = f2h2(L5.z, L5.w);
        unsigned h60 = f2h2(L6.x, L6.y), h61 = f2h2(L6.z, L6.w);
        unsigned h70 = f2h2(L7.x, L7.y), h71 = f2h2(L7.z, L7.w);

        unsigned u0, u1;
        #define FRAG(hA, hB, off, dst) \
            u0 = __shfl_sync(0xFFFFFFFFu, hA, srcA + (off)); \
            u1 = __shfl_sync(0xFFFFFFFFu, hB, srcA + (off)); \
            unsigned dst = hiP ? u1 : u0;

        // block0 fragments (rows rsub, rsub+8)
        FRAG(h00, h01, 0, aE0)  FRAG(h20, h21, 0, aE1)
        FRAG(h00, h01, 2, aE2)  FRAG(h20, h21, 2, aE3)
        FRAG(h10, h11, 0, aO0)  FRAG(h30, h31, 0, aO1)
        FRAG(h10, h11, 2, aO2)  FRAG(h30, h31, 2, aO3)
        // block1 fragments (rows rsub+16, rsub+24)
        FRAG(h40, h41, 0, bE0)  FRAG(h60, h61, 0, bE1)
        FRAG(h40, h41, 2, bE2)  FRAG(h60, h61, 2, bE3)
        FRAG(h50, h51, 0, bO0)  FRAG(h70, h71, 0, bO1)
        FRAG(h50, h51, 2, bO2)  FRAG(h70, h71, 2, bO3)
        #undef FRAG

        #pragma unroll
        for (int nt = 0; nt < 8; nt++) {
            uint4 bb = __ldg(&g_Wp[((nt * 128 + ks2) * 8) * 4 + lane]);
            mma16816(acc0[nt], aE0, aE1, aE2, aE3, bb.x, bb.y);
            mma16816(acc0[nt], aO0, aO1, aO2, aO3, bb.z, bb.w);
            mma16816(acc1[nt], bE0, bE1, bE2, bE3, bb.x, bb.y);
            mma16816(acc1[nt], bO0, bO1, bO2, bO3, bb.z, bb.w);
        }
    }

    // ---- scores to smem ----
    {
        int r = 32 * wid + rsub;
        int cb = 2 * q;
        #pragma unroll
        for (int nt = 0; nt < 8; nt++) {
            int c = 8 * nt + cb;
            sc[r * 68 + c]              = acc0[nt][0];
            sc[r * 68 + c + 1]          = acc0[nt][1];
            sc[(r + 8) * 68 + c]        = acc0[nt][2];
            sc[(r + 8) * 68 + c + 1]    = acc0[nt][3];
            sc[(r + 16) * 68 + c]       = acc1[nt][0];
            sc[(r + 16) * 68 + c + 1]   = acc1[nt][1];
            sc[(r + 24) * 68 + c]       = acc1[nt][2];
            sc[(r + 24) * 68 + c + 1]   = acc1[nt][3];
        }
    }
    __syncthreads();

    // ---- per-token top-8 scan, certify, write outputs, rescue ----
    {
        float sv[8];
        int   si[8];
        #pragma unroll
        for (int j = 0; j < 8; j++) { sv[j] = -INFINITY; si[j] = 0; }
        #pragma unroll
        for (int e = 0; e < NE; e++) {
            float cs = sc[tid * 68 + e] + s_bias[e];
            int ci = e;
            #pragma unroll
            for (int j = 0; j < 8; j++) {
                if (cs > sv[j]) {
                    float tf = sv[j]; int ti = si[j];
                    sv[j] = cs; si[j] = ci; cs = tf; ci = ti;
                }
            }
        }
        int token = row0 + tid;

        float e2v = expf(sv[1] - sv[0]);
        float inv = 1.0f / (1.0f + e2v);
        out[(size_t)token * 2 + 0] = inv;
        out[(size_t)token * 2 + 1] = e2v * inv;
        size_t idx_base = (size_t)n_tokens * 2;
        out[idx_base + (size_t)token * 2 + 0] = (float)si[0];
        out[idx_base + (size_t)token * 2 + 1] = (float)si[1];

        if ((sv[0] - sv[1] < TAU) || (sv[1] - sv[2] < TAU)) {
            int nc = 2;
            float thr = sv[1] - WIN;
            #pragma unroll
            for (int j = 2; j < 8; j++)
                if (sv[j] >= thr) nc = j + 1;
            int slot = atomicAdd(&g_count, 1);
            g_rtok[slot] = (unsigned)token | ((unsigned)nc << 20);
            unsigned lo = (unsigned)si[0] | ((unsigned)si[1] << 8) |
                          ((unsigned)si[2] << 16) | ((unsigned)si[3] << 24);
            unsigned hi = (unsigned)si[4] | ((unsigned)si[5] << 8) |
                          ((unsigned)si[6] << 16) | ((unsigned)si[7] << 24);
            g_rcand[slot] = make_uint2(lo, hi);
        }
    }
}

// ================= K3: warp-per-token exact fp32 rescore of the candidate window =================
__global__ __launch_bounds__(256, 4)
void k3_rescue(const float* __restrict__ X, const float* __restrict__ W,
               const float* __restrict__ b, float* __restrict__ out, int n_tokens)
{
    const int lane   = threadIdx.x & 31;
    const int gw     = (blockIdx.x * blockDim.x + threadIdx.x) >> 5;
    const int nwarps = (gridDim.x * blockDim.x) >> 5;
    const int cnt    = g_count;

    for (int it = gw; it < cnt; it += nwarps) {
        unsigned tv = g_rtok[it];
        const int token = tv & 0xFFFFF;
        const int nc    = tv >> 20;
        uint2 cd = g_rcand[it];
        int e[8];
        #pragma unroll
        for (int j = 0; j < 4; j++) e[j]     = (cd.x >> (8 * j)) & 63;
        #pragma unroll
        for (int j = 0; j < 4; j++) e[4 + j] = (cd.y >> (8 * j)) & 63;

        const float* xrow = X + (size_t)token * D_MODEL;

        float sum[8], cmp[8];
        #pragma unroll
        for (int j = 0; j < 8; j++) { sum[j] = 0.0f; cmp[j] = 0.0f; }

        for (int st = 0; st < D_MODEL / 128; st++) {       // 32 steps
            float4 xq = *(const float4*)(xrow + st * 128 + lane * 4);
            #pragma unroll
            for (int j = 0; j < 8; j++) {
                if (j >= nc) break;                        // warp-uniform
                float4 wq = __ldg((const float4*)(W + (size_t)e[j] * D_MODEL
                                                    + st * 128 + lane * 4));
                float s = xq.x * wq.x;
                s = fmaf(xq.y, wq.y, s);
                s = fmaf(xq.z, wq.z, s);
                s = fmaf(xq.w, wq.w, s);
                float y  = __fsub_rn(s, cmp[j]);
                float s2 = __fadd_rn(sum[j], y);
                cmp[j] = __fsub_rn(__fsub_rn(s2, sum[j]), y);
                sum[j] = s2;
            }
        }

        float m1 = -INFINITY, m2 = -INFINITY;
        int   i1 = 0,         i2 = 0;
        #pragma unroll
        for (int j = 0; j < 8; j++) {
            if (j >= nc) break;
            float s = __fadd_rn(sum[j], __fsub_rn(0.0f, cmp[j]));
            s = __fadd_rn(s, __shfl_xor_sync(0xFFFFFFFFu, s, 1));
            s = __fadd_rn(s, __shfl_xor_sync(0xFFFFFFFFu, s, 2));
            s = __fadd_rn(s, __shfl_xor_sync(0xFFFFFFFFu, s, 4));
            s = __fadd_rn(s, __shfl_xor_sync(0xFFFFFFFFu, s, 8));
            s = __fadd_rn(s, __shfl_xor_sync(0xFFFFFFFFu, s, 16));
            s = __fadd_rn(s, b[e[j]]);
            if (s > m1 || (s == m1 && e[j] < i1)) {
                m2 = m1; i2 = i1; m1 = s; i1 = e[j];
            } else if (s > m2 || (s == m2 && e[j] < i2)) {
                m2 = s; i2 = e[j];
            }
        }

        if (lane == 0) {
            float e2v = expf(m2 - m1);
            float inv = 1.0f / (1.0f + e2v);
            out[(size_t)token * 2 + 0] = inv;
            out[(size_t)token * 2 + 1] = e2v * inv;
            size_t idx_base = (size_t)n_tokens * 2;
            out[idx_base + (size_t)token * 2 + 0] = (float)i1;
            out[idx_base + (size_t)token * 2 + 1] = (float)i2;
        }
    }
}

// ================= launch =================
extern "C" void kernel_launch(void* const* d_in, const int* in_sizes, int n_in,
                              void* d_out, int out_size)
{
    const float* X = (const float*)d_in[0];   // [N, 4096]
    const float* W = (const float*)d_in[1];   // [64, 4096]
    const float* b = (const float*)d_in[2];   // [64]
    float* out = (float*)d_out;

    int n_tokens = in_sizes[0] / D_MODEL;     // 32768

    k0_permute_w<<<32, 256>>>(W);
    k1_screen<<<n_tokens / 128, 128>>>(X, b, out, n_tokens);
    k3_rescue<<<296, 256>>>(X, W, b, out, n_tokens);
}